// round 14
// baseline (speedup 1.0000x reference)
#include <cuda_runtime.h>
#include <cuda_bf16.h>
#include <cstdint>
#include <math.h>

#define NB 2
#define NS 2048
#define ND 1024
#define NH 16
#define NHD 64
#define NBS (NB*NS)        // 4096
#define THREE_D (3*ND)     // 3072

// ===================== helpers ==============================================
__device__ __forceinline__ uint32_t smem_u32(const void* p) {
    uint32_t a;
    asm("{ .reg .u64 t; cvta.to.shared.u64 t, %1; cvt.u32.u64 %0, t; }" : "=r"(a) : "l"(p));
    return a;
}
__device__ __forceinline__ void cp_async16(uint32_t s, const void* g) {
    asm volatile("cp.async.cg.shared.global [%0], [%1], 16;" :: "r"(s), "l"(g));
}
#define CP_COMMIT() asm volatile("cp.async.commit_group;" ::: "memory")
#define CP_WAIT1()  asm volatile("cp.async.wait_group 1;" ::: "memory")
#define CP_WAIT2()  asm volatile("cp.async.wait_group 2;" ::: "memory")
#define CP_WAIT0()  asm volatile("cp.async.wait_group 0;" ::: "memory")

__device__ __forceinline__ void ldsm_x4(uint32_t& r0, uint32_t& r1, uint32_t& r2, uint32_t& r3,
                                        uint32_t addr) {
    asm volatile("ldmatrix.sync.aligned.m8n8.x4.shared.b16 {%0,%1,%2,%3}, [%4];"
                 : "=r"(r0), "=r"(r1), "=r"(r2), "=r"(r3) : "r"(addr));
}
__device__ __forceinline__ void ldsm_x4t(uint32_t& r0, uint32_t& r1, uint32_t& r2, uint32_t& r3,
                                         uint32_t addr) {
    asm volatile("ldmatrix.sync.aligned.m8n8.x4.trans.shared.b16 {%0,%1,%2,%3}, [%4];"
                 : "=r"(r0), "=r"(r1), "=r"(r2), "=r"(r3) : "r"(addr));
}
__device__ __forceinline__ void mma16816(float* d, const uint32_t* a, uint32_t b0, uint32_t b1) {
    asm volatile(
        "mma.sync.aligned.m16n8k16.row.col.f32.bf16.bf16.f32 "
        "{%0,%1,%2,%3}, {%4,%5,%6,%7}, {%8,%9}, {%0,%1,%2,%3};"
        : "+f"(d[0]), "+f"(d[1]), "+f"(d[2]), "+f"(d[3])
        : "r"(a[0]), "r"(a[1]), "r"(a[2]), "r"(a[3]), "r"(b0), "r"(b1));
}
__device__ __forceinline__ uint32_t packbf(float lo, float hi) {
    uint32_t r;
    asm("cvt.rn.bf16x2.f32 %0, %1, %2;" : "=r"(r) : "f"(hi), "f"(lo));
    return r;
}

// ------------------------- scratch (allocation-free) -------------------------
__device__ float g_qkv[NBS*THREE_D];
__device__ float g_attnproj[NBS*ND];
__device__ float g_x1[NBS*ND];
__device__ float g_Q[NHD*NHD];
__device__ float g_cos[NS*NHD];
__device__ float g_sin[NS*NHD];
__device__ float g_wqkv_rot[(size_t)ND*THREE_D];   // w_qkv with Q^T folded into q,k cols
// attention operands (bf16): q/k = [hi(64) | lo(64)] per token, v hi/lo planes
__device__ __nv_bfloat16 g_qa[(size_t)NB*NH*NS*128];
__device__ __nv_bfloat16 g_ka[(size_t)NB*NH*NS*128];
__device__ __nv_bfloat16 g_vh2[(size_t)NB*NH*NS*64];
__device__ __nv_bfloat16 g_vl2[(size_t)NB*NH*NS*64];
// split-bf16 activations: [M, 2K] = [hi | lo]  (third GEMM term wraps to hi)
__device__ __nv_bfloat16 g_h_aug[(size_t)NBS*2*ND];
__device__ __nv_bfloat16 g_attn_aug[(size_t)NBS*2*ND];
__device__ __nv_bfloat16 g_ap_aug[(size_t)NBS*2*ND];
__device__ __nv_bfloat16 g_h2_aug[(size_t)NBS*2*ND];
__device__ __nv_bfloat16 g_t_aug[(size_t)NBS*8*ND];
// augmented transposed weights: [N, 3K] = [hi | hi | lo]
__device__ __nv_bfloat16 g_wqkvT[3*ND*3*ND];
__device__ __nv_bfloat16 g_woutT[ND*3*ND];
__device__ __nv_bfloat16 g_wgateT[ND*3*ND];
__device__ __nv_bfloat16 g_wmgT[(size_t)8*ND*3*ND];   // column-permuted (g/val interleave)
__device__ __nv_bfloat16 g_wmoT[(size_t)ND*12*ND];

// ======================= split helpers ======================================
__device__ __forceinline__ void split_hi_lo(float v, __nv_bfloat16& hi, __nv_bfloat16& lo) {
    hi = __float2bfloat16(v);
    lo = __float2bfloat16(v - __bfloat162float(hi));
}
__device__ __forceinline__ void store_aug4(__nv_bfloat16* base, size_t rowbase, int K, int col,
                                           float v0, float v1, float v2, float v3) {
    __nv_bfloat16 h[4], l[4];
    split_hi_lo(v0, h[0], l[0]); split_hi_lo(v1, h[1], l[1]);
    split_hi_lo(v2, h[2], l[2]); split_hi_lo(v3, h[3], l[3]);
    __nv_bfloat162 p;
    p.x = h[0]; p.y = h[1]; *(__nv_bfloat162*)(base + rowbase + col) = p;
    p.x = h[2]; p.y = h[3]; *(__nv_bfloat162*)(base + rowbase + col + 2) = p;
    p.x = l[0]; p.y = l[1]; *(__nv_bfloat162*)(base + rowbase + K + col) = p;
    p.x = l[2]; p.y = l[3]; *(__nv_bfloat162*)(base + rowbase + K + col + 2) = p;
}
__device__ __forceinline__ void store_aug2(__nv_bfloat16* base, size_t rowbase, int K, int col,
                                           float v0, float v1) {
    __nv_bfloat16 h0, l0, h1, l1;
    split_hi_lo(v0, h0, l0); split_hi_lo(v1, h1, l1);
    __nv_bfloat162 p;
    p.x = h0; p.y = h1; *(__nv_bfloat162*)(base + rowbase + col) = p;
    p.x = l0; p.y = l1; *(__nv_bfloat162*)(base + rowbase + K + col) = p;
}

// ------------------------- rmsnorm -> split bf16 ----------------------------
__global__ __launch_bounds__(256)
void rmsnorm_split_kernel(const float* __restrict__ x, __nv_bfloat16* __restrict__ o) {
    int row = blockIdx.x;
    const float4* xr = (const float4*)(x + (size_t)row * ND);
    float4 v = xr[threadIdx.x];
    float ss = v.x*v.x + v.y*v.y + v.z*v.z + v.w*v.w;
    #pragma unroll
    for (int m = 16; m > 0; m >>= 1) ss += __shfl_xor_sync(0xffffffffu, ss, m);
    __shared__ float sred[8];
    if ((threadIdx.x & 31) == 0) sred[threadIdx.x >> 5] = ss;
    __syncthreads();
    float tot = 0.f;
    #pragma unroll
    for (int i = 0; i < 8; i++) tot += sred[i];
    float r = rsqrtf(tot * (1.0f / ND) + 1e-6f);
    store_aug4(o, (size_t)row * 2 * ND, ND, threadIdx.x * 4, v.x*r, v.y*r, v.z*r, v.w*r);
}

// ------------------- weight transpose + split (K,N)->(N,3K) -----------------
__device__ __forceinline__ void transpose_split_body(const float* __restrict__ B,
                                                     __nv_bfloat16* __restrict__ out,
                                                     int K, int N, int bx, int by) {
    __shared__ float sm[64][33];
    int k0 = bx * 64, n0 = by * 32;
    int tx = threadIdx.x, ty = threadIdx.y;
    int lin = ty * 32 + tx;
    #pragma unroll
    for (int e = 0; e < 2; e++) {
        int idx = lin + e * 1024;
        int kk = idx >> 5, nn = idx & 31;
        sm[kk][nn] = B[(size_t)(k0 + kk) * N + n0 + nn];
    }
    __syncthreads();
    int n = n0 + ty;
    int kk = 2 * tx;
    float v0 = sm[kk][ty], v1 = sm[kk + 1][ty];
    __nv_bfloat16 h0, l0, h1, l1;
    split_hi_lo(v0, h0, l0); split_hi_lo(v1, h1, l1);
    size_t base = (size_t)n * 3 * K;
    __nv_bfloat162 p;
    p.x = h0; p.y = h1;
    *(__nv_bfloat162*)(out + base + k0 + kk) = p;
    *(__nv_bfloat162*)(out + base + K + k0 + kk) = p;
    p.x = l0; p.y = l1;
    *(__nv_bfloat162*)(out + base + 2 * K + k0 + kk) = p;
}

__global__ __launch_bounds__(1024)
void transpose_split_kernel(const float* __restrict__ B, __nv_bfloat16* __restrict__ out,
                            int K, int N) {
    transpose_split_body(B, out, K, N, blockIdx.x, blockIdx.y);
}

// merged launch: w_out (512 blocks), w_gate (512), w_mlp_out (2048)
__global__ __launch_bounds__(1024)
void transpose_split_multi_kernel(const float* __restrict__ B0, __nv_bfloat16* __restrict__ o0,
                                  const float* __restrict__ B1, __nv_bfloat16* __restrict__ o1,
                                  const float* __restrict__ B2, __nv_bfloat16* __restrict__ o2) {
    int lin = blockIdx.x;
    if (lin < 512) {
        transpose_split_body(B0, o0, 1024, 1024, lin & 15, lin >> 4);
    } else if (lin < 1024) {
        int r = lin - 512;
        transpose_split_body(B1, o1, 1024, 1024, r & 15, r >> 4);
    } else {
        int r = lin - 1024;
        transpose_split_body(B2, o2, 4096, 1024, r & 63, r >> 6);
    }
}

// --- permuted variant for w_mlp_gate: out row n <- source col perm(n) -------
__global__ __launch_bounds__(1024)
void transpose_split_perm_kernel(const float* __restrict__ B, __nv_bfloat16* __restrict__ out,
                                 int K, int N) {
    __shared__ float sm[64][33];
    int k0 = blockIdx.x * 64, n0 = blockIdx.y * 32;
    int tx = threadIdx.x, ty = threadIdx.y;
    int lin = ty * 32 + tx;
    #pragma unroll
    for (int e = 0; e < 2; e++) {
        int idx = lin + e * 1024;
        int kk = idx >> 5, nn = idx & 31;
        int n = n0 + nn;
        int src = (n & 1) ? (n >> 1) + (N >> 1) : (n >> 1);
        sm[kk][nn] = B[(size_t)(k0 + kk) * N + src];
    }
    __syncthreads();
    int n = n0 + ty;
    int kk = 2 * tx;
    float v0 = sm[kk][ty], v1 = sm[kk + 1][ty];
    __nv_bfloat16 h0, l0, h1, l1;
    split_hi_lo(v0, h0, l0); split_hi_lo(v1, h1, l1);
    size_t base = (size_t)n * 3 * K;
    __nv_bfloat162 p;
    p.x = h0; p.y = h1;
    *(__nv_bfloat162*)(out + base + k0 + kk) = p;
    *(__nv_bfloat162*)(out + base + K + k0 + kk) = p;
    p.x = l0; p.y = l1;
    *(__nv_bfloat162*)(out + base + 2 * K + k0 + kk) = p;
}

// ----------------------- Householder Q (64x64) ------------------------------
__global__ void buildQ_kernel(const float* __restrict__ vs) {
    __shared__ float Qm[NHD][NHD];
    __shared__ float vv[NHD];
    int t = threadIdx.x;
    #pragma unroll
    for (int i = 0; i < NHD; i++) Qm[i][t] = (i == t) ? 1.f : 0.f;
    for (int r = 0; r < 32; r++) {
        __syncthreads();
        vv[t] = vs[r * NHD + t];
        __syncthreads();
        float w = 0.f, vn = 0.f;
        #pragma unroll
        for (int i = 0; i < NHD; i++) { w += vv[i] * Qm[i][t]; vn += vv[i] * vv[i]; }
        float c = 2.0f / (vn + 1e-8f);
        #pragma unroll
        for (int i = 0; i < NHD; i++) Qm[i][t] -= c * vv[i] * w;
    }
    __syncthreads();
    for (int i = 0; i < NHD; i++) g_Q[i * NHD + t] = Qm[i][t];
}

// ---- fold Q^T into q,k columns of w_qkv: W'[:, hd, j] = sum_d W[:, hd, d]*Q[j,d]
__global__ __launch_bounds__(64)
void premul_qkv_kernel(const float* __restrict__ W, float* __restrict__ Wr) {
    int k = blockIdx.x, slot = blockIdx.y;   // slot 0..31 = q,k head slots; 32..47 = v copy
    int j = threadIdx.x;
    const float* src = W + (size_t)k * THREE_D + slot * 64;
    if (slot >= 32) { Wr[(size_t)k * THREE_D + slot * 64 + j] = src[j]; return; }
    __shared__ float wrow[64];
    wrow[j] = src[j];
    __syncthreads();
    float acc = 0.f;
    #pragma unroll 16
    for (int d = 0; d < 64; d++) acc += wrow[d] * g_Q[j * 64 + d];
    Wr[(size_t)k * THREE_D + slot * 64 + j] = acc;
}

// ----------------------------- rope tables ----------------------------------
__global__ void rope_tables_kernel() {
    int s = blockIdx.x;
    int d = threadIdx.x;
    int i = d & 31;
    float invf = powf(10000.0f, -(float)(2 * i) / 64.0f);
    float ang = (float)s * invf;
    g_cos[s * NHD + d] = cosf(ang);
    g_sin[s * NHD + d] = sinf(ang);
}

// --- RoPE (elementwise; rotation pre-folded into weights, post-rotation
//     cancels by orthogonality in QK^T) + head transpose + split bf16 --------
__global__ __launch_bounds__(256)
void rope_apply_kernel(const float* __restrict__ qkv) {
    int bs = blockIdx.x;
    int which = blockIdx.y;
    int b = bs >> 11, s = bs & 2047;
    int tid = threadIdx.x;
    int lane = tid & 63, grp = tid >> 6;

    if (which == 2) {
        #pragma unroll
        for (int hh = 0; hh < 4; hh++) {
            int h = grp * 4 + hh;
            int bh = b * NH + h;
            float v = qkv[(size_t)bs * THREE_D + 2 * ND + h * NHD + lane];
            __nv_bfloat16 hi, lo; split_hi_lo(v, hi, lo);
            size_t base = ((size_t)bh * NS + s) * 64 + lane;
            g_vh2[base] = hi;
            g_vl2[base] = lo;
        }
        return;
    }
    __shared__ float xb[4][2][NHD];
    float cs = g_cos[s * NHD + lane], sn = g_sin[s * NHD + lane];
    const float* src = qkv + (size_t)bs * THREE_D + which * ND;
    __nv_bfloat16* dst = (which == 0) ? g_qa : g_ka;
    const float qs = (which == 0) ? 0.125f : 1.0f;   // fold 1/sqrt(d) into q (exact pow2)
    #pragma unroll
    for (int hh = 0; hh < 4; hh++) {
        int h = grp * 4 + hh;
        int pb = hh & 1;
        xb[grp][pb][lane] = src[h * NHD + lane];
        __syncthreads();
        float val = xb[grp][pb][lane];
        float prt = xb[grp][pb][lane ^ 32];
        float rot = (lane < 32) ? -prt : prt;
        float o = (val * cs + rot * sn) * qs;
        int bh = b * NH + h;
        __nv_bfloat16 hi, lo; split_hi_lo(o, hi, lo);
        size_t base = ((size_t)bh * NS + s) * 128;
        dst[base + lane] = hi;
        dst[base + 64 + lane] = lo;
    }
}

// ==================== HMMA flash attention v2 ===============================
#define FQB 272                       // Q/K smem row stride bytes (136 bf16)
#define FVB 144                       // V smem row stride bytes (72 bf16)
#define FK_BYTES (64*FQB)             // 17408
#define FV_BYTES (64*FVB)             // 9216
#define FBUF (FK_BYTES + 2*FV_BYTES)  // 35840
#define FLS_SMEM (128*FQB + 2*FBUF)   // 106496

__global__ __launch_bounds__(256)
void flash_hmma_kernel() {
    extern __shared__ char smf[];
    const int qt = (NS / 128) - 1 - blockIdx.x;    // heavy tiles first
    const int bh = blockIdx.y;
    const int b = bh >> 4, hd = bh & 15;
    const int tid = threadIdx.x;
    const int w = tid >> 5, lane = tid & 31;
    const uint32_t sb = smem_u32(smf);
    const uint32_t sQ = sb;

    const __nv_bfloat16* qg = g_qa + ((size_t)bh * NS + (size_t)qt * 128) * 128;
    const __nv_bfloat16* kg = g_ka + (size_t)bh * NS * 128;
    const __nv_bfloat16* vhg = g_vh2 + (size_t)bh * NS * 64;
    const __nv_bfloat16* vlg = g_vl2 + (size_t)bh * NS * 64;

    #pragma unroll
    for (int i = 0; i < 8; i++) {
        int ch = tid + i * 256; int r = ch >> 4, c = ch & 15;
        cp_async16(sQ + r * FQB + c * 16, qg + (size_t)r * 128 + c * 8);
    }
    CP_COMMIT();

    auto load_kv = [&](int kt, int buf) {
        uint32_t sK = sb + 128 * FQB + buf * FBUF;
        uint32_t sVh = sK + FK_BYTES;
        uint32_t sVl = sVh + FV_BYTES;
        #pragma unroll
        for (int i = 0; i < 4; i++) {
            int ch = tid + i * 256; int r = ch >> 4, c = ch & 15;
            cp_async16(sK + r * FQB + c * 16, kg + (size_t)(kt * 64 + r) * 128 + c * 8);
        }
        #pragma unroll
        for (int i = 0; i < 2; i++) {
            int ch = tid + i * 256; int r = ch >> 3, c = ch & 7;
            cp_async16(sVh + r * FVB + c * 16, vhg + (size_t)(kt * 64 + r) * 64 + c * 8);
            cp_async16(sVl + r * FVB + c * 16, vlg + (size_t)(kt * 64 + r) * 64 + c * 8);
        }
        CP_COMMIT();
    };

    const int nkv = (qt + 1) * 2;
    load_kv(0, 0);
    CP_WAIT1();
    __syncthreads();

    const int a_r = lane & 15, a_c = (lane >> 4) * 8;
    uint32_t qf[8][4];
    #pragma unroll
    for (int ks = 0; ks < 8; ks++) {
        uint32_t addr = sQ + (uint32_t)((w * 16 + a_r) * FQB + (ks * 16 + a_c) * 2);
        ldsm_x4(qf[ks][0], qf[ks][1], qf[ks][2], qf[ks][3], addr);
    }

    float oacc[8][4];
    #pragma unroll
    for (int j = 0; j < 8; j++)
        #pragma unroll
        for (int e = 0; e < 4; e++) oacc[j][e] = 0.f;
    float mrow[2] = {-1e30f, -1e30f}, lrow[2] = {0.f, 0.f};

    const int b_g = lane >> 3, b_r2 = (b_g >> 1) * 8 + (lane & 7), b_c = (b_g & 1) * 8;
    const int vg = lane >> 3, vw = lane & 7;
    const int v_r = (vg & 1) * 8 + vw, v_c = (vg >> 1) * 8;

    for (int kt = 0; kt < nkv; kt++) {
        if (kt + 1 < nkv) { load_kv(kt + 1, (kt + 1) & 1); CP_WAIT1(); }
        else { CP_WAIT0(); }
        __syncthreads();
        uint32_t sK = sb + 128 * FQB + (kt & 1) * FBUF;
        uint32_t sVh = sK + FK_BYTES, sVl = sVh + FV_BYTES;

        float sacc[8][4];
        #pragma unroll
        for (int j = 0; j < 8; j++)
            #pragma unroll
            for (int e = 0; e < 4; e++) sacc[j][e] = 0.f;
        #pragma unroll
        for (int ks = 0; ks < 4; ks++) {
            uint32_t bfr[4][4];
            #pragma unroll
            for (int nb = 0; nb < 4; nb++) {
                uint32_t addr = sK + (uint32_t)((nb * 16 + b_r2) * FQB + (ks * 16 + b_c) * 2);
                ldsm_x4(bfr[nb][0], bfr[nb][1], bfr[nb][2], bfr[nb][3], addr);
            }
            #pragma unroll
            for (int j = 0; j < 8; j++) {
                mma16816(sacc[j], qf[ks],     bfr[j >> 1][(j & 1) * 2], bfr[j >> 1][(j & 1) * 2 + 1]);
                mma16816(sacc[j], qf[ks + 4], bfr[j >> 1][(j & 1) * 2], bfr[j >> 1][(j & 1) * 2 + 1]);
            }
        }
        #pragma unroll
        for (int ks = 0; ks < 4; ks++) {
            uint32_t bfr[4][4];
            #pragma unroll
            for (int nb = 0; nb < 4; nb++) {
                uint32_t addr = sK + (uint32_t)((nb * 16 + b_r2) * FQB + (64 + ks * 16 + b_c) * 2);
                ldsm_x4(bfr[nb][0], bfr[nb][1], bfr[nb][2], bfr[nb][3], addr);
            }
            #pragma unroll
            for (int j = 0; j < 8; j++)
                mma16816(sacc[j], qf[ks], bfr[j >> 1][(j & 1) * 2], bfr[j >> 1][(j & 1) * 2 + 1]);
        }

        // ---- online softmax (scale pre-folded into q) ----
        #pragma unroll
        for (int hf = 0; hf < 2; hf++) {
            float mt = -1e30f;
            #pragma unroll
            for (int j = 0; j < 8; j++)
                mt = fmaxf(mt, fmaxf(sacc[j][2*hf], sacc[j][2*hf+1]));
            mt = fmaxf(mt, __shfl_xor_sync(0xffffffffu, mt, 1));
            mt = fmaxf(mt, __shfl_xor_sync(0xffffffffu, mt, 2));
            float mn = fmaxf(mrow[hf], mt);
            float alpha = __expf(mrow[hf] - mn);
            mrow[hf] = mn;
            float lt = 0.f;
            #pragma unroll
            for (int j = 0; j < 8; j++) {
                float p0 = __expf(sacc[j][2*hf] - mn);
                float p1 = __expf(sacc[j][2*hf+1] - mn);
                sacc[j][2*hf] = p0; sacc[j][2*hf+1] = p1;
                lt += p0 + p1;
            }
            lt += __shfl_xor_sync(0xffffffffu, lt, 1);
            lt += __shfl_xor_sync(0xffffffffu, lt, 2);
            lrow[hf] = lrow[hf] * alpha + lt;
            #pragma unroll
            for (int j = 0; j < 8; j++) { oacc[j][2*hf] *= alpha; oacc[j][2*hf+1] *= alpha; }
        }

        uint32_t ahi[4][4], alo[4][4];
        #pragma unroll
        for (int kk = 0; kk < 4; kk++) {
            #pragma unroll
            for (int q = 0; q < 4; q++) {
                int j = 2 * kk + (q >> 1);
                float p0 = sacc[j][(q & 1) * 2], p1 = sacc[j][(q & 1) * 2 + 1];
                float h0 = __bfloat162float(__float2bfloat16(p0));
                float h1 = __bfloat162float(__float2bfloat16(p1));
                ahi[kk][q] = packbf(h0, h1);
                alo[kk][q] = packbf(p0 - h0, p1 - h1);
            }
        }

        #pragma unroll
        for (int kk = 0; kk < 4; kk++) {
            uint32_t bfh[4][4];
            #pragma unroll
            for (int nb = 0; nb < 4; nb++) {
                uint32_t addr = sVh + (uint32_t)((kk * 16 + v_r) * FVB + (nb * 16 + v_c) * 2);
                ldsm_x4t(bfh[nb][0], bfh[nb][1], bfh[nb][2], bfh[nb][3], addr);
            }
            #pragma unroll
            for (int j = 0; j < 8; j++) {
                mma16816(oacc[j], ahi[kk], bfh[j >> 1][(j & 1) * 2], bfh[j >> 1][(j & 1) * 2 + 1]);
                mma16816(oacc[j], alo[kk], bfh[j >> 1][(j & 1) * 2], bfh[j >> 1][(j & 1) * 2 + 1]);
            }
            uint32_t bfl[4][4];
            #pragma unroll
            for (int nb = 0; nb < 4; nb++) {
                uint32_t addr = sVl + (uint32_t)((kk * 16 + v_r) * FVB + (nb * 16 + v_c) * 2);
                ldsm_x4t(bfl[nb][0], bfl[nb][1], bfl[nb][2], bfl[nb][3], addr);
            }
            #pragma unroll
            for (int j = 0; j < 8; j++)
                mma16816(oacc[j], ahi[kk], bfl[j >> 1][(j & 1) * 2], bfl[j >> 1][(j & 1) * 2 + 1]);
        }
        __syncthreads();
    }

    float inv0 = 1.f / lrow[0], inv1 = 1.f / lrow[1];
    int r0 = qt * 128 + w * 16 + (lane >> 2);
    size_t row0 = (size_t)(b * NS + r0) * 2 * ND;
    size_t row1 = row0 + (size_t)8 * 2 * ND;
    #pragma unroll
    for (int j = 0; j < 8; j++) {
        int col = hd * 64 + j * 8 + (lane & 3) * 2;
        store_aug2(g_attn_aug, row0, ND, col, oacc[j][0] * inv0, oacc[j][1] * inv0);
        store_aug2(g_attn_aug, row1, ND, col, oacc[j][2] * inv1, oacc[j][3] * inv1);
    }
}

// ====================== HMMA bf16 GEMM (4-stage, A-wrap) ====================
#define HG_PAD    40
#define HG_STAGE  (2 * 128 * HG_PAD * 2)   // 20480
#define HG_SMEM   (4 * HG_STAGE)           // 81920

template<int EPI>
__global__ __launch_bounds__(256)
void hmma_gemm(const __nv_bfloat16* __restrict__ A, const __nv_bfloat16* __restrict__ Bt,
               float* __restrict__ C, int M, int N, int Kb,
               const float* __restrict__ bias,
               const float* __restrict__ e1, const float* __restrict__ e2)
{
    extern __shared__ char smc[];
    const int tid = threadIdx.x;
    const int wid = tid >> 5, lane = tid & 31;
    const int m0 = blockIdx.y * 128, n0 = blockIdx.x * 128;
    const int wm = (wid >> 2) * 64, wn = (wid & 3) * 32;
    const uint32_t sbase = smem_u32(smc);
    const int Kp = 3 * Kb;
    const int Ka = 2 * Kb;

    const int q0 = tid, q1 = tid + 256;
    const int ra0 = q0 >> 2, ca0 = (q0 & 3);
    const int ra1 = q1 >> 2, ca1 = (q1 & 3);

    auto load_stage = [&](int s, int kk) {
        int kka = (kk >= Ka) ? kk - Ka : kk;
        uint32_t aS = sbase + s * HG_STAGE;
        uint32_t bS = aS + 128 * HG_PAD * 2;
        cp_async16(aS + ra0 * 80 + ca0 * 16, A + (size_t)(m0 + ra0) * Ka + kka + ca0 * 8);
        cp_async16(aS + ra1 * 80 + ca1 * 16, A + (size_t)(m0 + ra1) * Ka + kka + ca1 * 8);
        cp_async16(bS + ra0 * 80 + ca0 * 16, Bt + (size_t)(n0 + ra0) * Kp + kk + ca0 * 8);
        cp_async16(bS + ra1 * 80 + ca1 * 16, Bt + (size_t)(n0 + ra1) * Kp + kk + ca1 * 8);
        CP_COMMIT();
    };

    const int KT = Kp >> 5;
    load_stage(0, 0);
    load_stage(1, 32);
    load_stage(2, 64);

    float acc[16][4];
    #pragma unroll
    for (int f = 0; f < 16; f++)
        #pragma unroll
        for (int e = 0; e < 4; e++) acc[f][e] = 0.f;

    const int a_r = (lane & 15);
    const int a_c = (lane >> 4) * 8;
    const int b_g = lane >> 3;
    const int b_r = (b_g >> 1) * 8 + (lane & 7);
    const int b_c = (b_g & 1) * 8;

    for (int kt = 0; kt < KT; kt++) {
        CP_WAIT2();
        __syncthreads();
        if (kt + 3 < KT) load_stage((kt + 3) & 3, (kt + 3) * 32);

        uint32_t aS = sbase + (kt & 3) * HG_STAGE;
        uint32_t bS = aS + 128 * HG_PAD * 2;

        #pragma unroll
        for (int ks = 0; ks < 2; ks++) {
            uint32_t af[4][4];
            #pragma unroll
            for (int mf = 0; mf < 4; mf++) {
                uint32_t addr = aS + (uint32_t)((wm + mf * 16 + a_r) * 80 + (ks * 16 + a_c) * 2);
                ldsm_x4(af[mf][0], af[mf][1], af[mf][2], af[mf][3], addr);
            }
            uint32_t bfr[2][4];
            #pragma unroll
            for (int nb = 0; nb < 2; nb++) {
                uint32_t addr = bS + (uint32_t)((wn + nb * 16 + b_r) * 80 + (ks * 16 + b_c) * 2);
                ldsm_x4(bfr[nb][0], bfr[nb][1], bfr[nb][2], bfr[nb][3], addr);
            }
            #pragma unroll
            for (int mf = 0; mf < 4; mf++)
                #pragma unroll
                for (int nf = 0; nf < 4; nf++) {
                    int nb = nf >> 1, pr = (nf & 1) * 2;
                    mma16816(acc[mf * 4 + nf], af[mf], bfr[nb][pr], bfr[nb][pr + 1]);
                }
        }
    }

    #pragma unroll
    for (int mf = 0; mf < 4; mf++) {
        #pragma unroll
        for (int nf = 0; nf < 4; nf++) {
            float* a = acc[mf * 4 + nf];
            int col = n0 + wn + nf * 8 + (lane & 3) * 2;
            #pragma unroll
            for (int half = 0; half < 2; half++) {
                int row = m0 + wm + mf * 16 + (lane >> 2) + half * 8;
                size_t idx = (size_t)row * N + col;
                float v0 = a[half * 2], v1 = a[half * 2 + 1];
                if (EPI == 0) {
                    if (bias) { v0 += bias[col]; v1 += bias[col + 1]; }
                    *(float2*)(C + idx) = make_float2(v0, v1);
                } else if (EPI == 1) {
                    float g0 = 1.f / (1.f + __expf(-(v0 + bias[col])));
                    float g1 = 1.f / (1.f + __expf(-(v1 + bias[col + 1])));
                    float2 ee1 = *(const float2*)(e1 + idx);
                    float2 ee2 = *(const float2*)(e2 + idx);
                    *(float2*)(C + idx) = make_float2(ee2.x + ee1.x * g0, ee2.y + ee1.y * g1);
                } else if (EPI == 2) {
                    float2 ee2 = *(const float2*)(e2 + idx);
                    *(float2*)(C + idx) = make_float2(ee2.x + v0 + bias[col],
                                                      ee2.y + v1 + bias[col + 1]);
                } else if (EPI == 3) {
                    *(float2*)(C + idx) = make_float2(v0, v1);
                    __nv_bfloat16* Ca = (__nv_bfloat16*)(uintptr_t)e1;
                    store_aug2(Ca, (size_t)row * 2 * N, N, col, v0, v1);
                } else {
                    int j = col >> 1;
                    float g = v0 + bias[j];
                    float vv = v1 + bias[j + (N >> 1)];
                    float t = vv * (0.5f * g * (1.f + erff(g * 0.70710678118654752f)));
                    __nv_bfloat16 hi, lo; split_hi_lo(t, hi, lo);
                    __nv_bfloat16* T = (__nv_bfloat16*)(uintptr_t)e1;
                    size_t rb = (size_t)row * N;
                    T[rb + j] = hi;
                    T[rb + (N >> 1) + j] = lo;
                }
            }
        }
    }
}

// --------------------------------- launcher ---------------------------------
extern "C" void kernel_launch(void* const* d_in, const int* in_sizes, int n_in,
                              void* d_out, int out_size) {
    const float* x          = (const float*)d_in[0];
    const float* vs         = (const float*)d_in[3];
    const float* w_qkv      = (const float*)d_in[4];
    const float* w_out      = (const float*)d_in[5];
    const float* w_gate     = (const float*)d_in[6];
    const float* b_gate     = (const float*)d_in[7];
    const float* w_mlp_gate = (const float*)d_in[8];
    const float* b_mlp_gate = (const float*)d_in[9];
    const float* w_mlp_out  = (const float*)d_in[10];
    const float* b_mlp_out  = (const float*)d_in[11];
    float* out = (float*)d_out;

    float *p_qkv, *p_attnproj, *p_x1, *p_wrot;
    __nv_bfloat16 *p_h_aug, *p_attn_aug, *p_ap_aug, *p_h2_aug, *p_t_aug;
    __nv_bfloat16 *p_wqkvT, *p_woutT, *p_wgateT, *p_wmgT, *p_wmoT;
    cudaGetSymbolAddress((void**)&p_qkv, g_qkv);
    cudaGetSymbolAddress((void**)&p_attnproj, g_attnproj);
    cudaGetSymbolAddress((void**)&p_x1, g_x1);
    cudaGetSymbolAddress((void**)&p_wrot, g_wqkv_rot);
    cudaGetSymbolAddress((void**)&p_h_aug, g_h_aug);
    cudaGetSymbolAddress((void**)&p_attn_aug, g_attn_aug);
    cudaGetSymbolAddress((void**)&p_ap_aug, g_ap_aug);
    cudaGetSymbolAddress((void**)&p_h2_aug, g_h2_aug);
    cudaGetSymbolAddress((void**)&p_t_aug, g_t_aug);
    cudaGetSymbolAddress((void**)&p_wqkvT, g_wqkvT);
    cudaGetSymbolAddress((void**)&p_woutT, g_woutT);
    cudaGetSymbolAddress((void**)&p_wgateT, g_wgateT);
    cudaGetSymbolAddress((void**)&p_wmgT, g_wmgT);
    cudaGetSymbolAddress((void**)&p_wmoT, g_wmoT);

    cudaFuncSetAttribute(flash_hmma_kernel, cudaFuncAttributeMaxDynamicSharedMemorySize, FLS_SMEM);
    cudaFuncSetAttribute(hmma_gemm<0>, cudaFuncAttributeMaxDynamicSharedMemorySize, HG_SMEM);
    cudaFuncSetAttribute(hmma_gemm<1>, cudaFuncAttributeMaxDynamicSharedMemorySize, HG_SMEM);
    cudaFuncSetAttribute(hmma_gemm<2>, cudaFuncAttributeMaxDynamicSharedMemorySize, HG_SMEM);
    cudaFuncSetAttribute(hmma_gemm<3>, cudaFuncAttributeMaxDynamicSharedMemorySize, HG_SMEM);
    cudaFuncSetAttribute(hmma_gemm<4>, cudaFuncAttributeMaxDynamicSharedMemorySize, HG_SMEM);

    dim3 t32(32, 32);
    // Q build + fold Q^T into q,k weight columns
    buildQ_kernel<<<1, 64>>>(vs);
    premul_qkv_kernel<<<dim3(ND, 48), 64>>>(w_qkv, p_wrot);
    transpose_split_kernel<<<dim3(ND/64, THREE_D/32), t32>>>(p_wrot, p_wqkvT, ND, THREE_D);
    transpose_split_multi_kernel<<<3072, t32>>>(w_out, p_woutT, w_gate, p_wgateT,
                                                w_mlp_out, p_wmoT);
    transpose_split_perm_kernel<<<dim3(ND/64, 8*ND/32), t32>>>(w_mlp_gate, p_wmgT, ND, 8*ND);
    rope_tables_kernel<<<NS, 64>>>();

    // 1. h = split(rmsnorm(x))  [hi|lo]
    rmsnorm_split_kernel<<<NBS, 256>>>(x, p_h_aug);
    // 2. qkv = h @ w_qkv_rot  (q,k already rotated)
    hmma_gemm<0><<<dim3(THREE_D/128, NBS/128), 256, HG_SMEM>>>(
        p_h_aug, p_wqkvT, p_qkv, NBS, THREE_D, ND, nullptr, nullptr, nullptr);
    // 3. elementwise RoPE + head transpose -> split bf16 operands (q pre-scaled)
    rope_apply_kernel<<<dim3(NBS, 3), 256>>>(p_qkv);
    // 4. attention (HMMA) -> attn [hi|lo]  (post-rotation cancels in QK^T)
    flash_hmma_kernel<<<dim3(NS/128, NB*NH), 256, FLS_SMEM>>>();
    // 5. attnproj = attn @ w_out  (+ fused [hi|lo] split)
    hmma_gemm<3><<<dim3(ND/128, NBS/128), 256, HG_SMEM>>>(
        p_attn_aug, p_woutT, p_attnproj, NBS, ND, ND, nullptr,
        (const float*)p_ap_aug, nullptr);
    // 6. x1 = x + attnproj * sigmoid(attnproj @ w_gate + b_gate)
    hmma_gemm<1><<<dim3(ND/128, NBS/128), 256, HG_SMEM>>>(
        p_ap_aug, p_wgateT, p_x1, NBS, ND, ND, b_gate, p_attnproj, x);
    // 7. h2 = split(rmsnorm(x1))
    rmsnorm_split_kernel<<<NBS, 256>>>(p_x1, p_h2_aug);
    // 8. fused mlp_gate GEMM + GLU -> t [hi|lo]   (permuted weights)
    hmma_gemm<4><<<dim3(8*ND/128, NBS/128), 256, HG_SMEM>>>(
        p_h2_aug, p_wmgT, p_x1 /*unused*/, NBS, 8*ND, ND, b_mlp_gate,
        (const float*)p_t_aug, nullptr);
    // 9. out = x1 + t @ w_mlp_out + b
    hmma_gemm<2><<<dim3(ND/128, NBS/128), 256, HG_SMEM>>>(
        p_t_aug, p_wmoT, out, NBS, ND, 4*ND, b_mlp_out, nullptr, p_x1);
}

// round 15
// speedup vs baseline: 1.2270x; 1.2270x over previous
#include <cuda_runtime.h>
#include <cuda_bf16.h>
#include <cstdint>
#include <math.h>

#define NB 2
#define NS 2048
#define ND 1024
#define NH 16
#define NHD 64
#define NBS (NB*NS)        // 4096
#define THREE_D (3*ND)     // 3072

// ===================== helpers ==============================================
__device__ __forceinline__ uint32_t smem_u32(const void* p) {
    uint32_t a;
    asm("{ .reg .u64 t; cvta.to.shared.u64 t, %1; cvt.u32.u64 %0, t; }" : "=r"(a) : "l"(p));
    return a;
}
__device__ __forceinline__ void cp_async16(uint32_t s, const void* g) {
    asm volatile("cp.async.cg.shared.global [%0], [%1], 16;" :: "r"(s), "l"(g));
}
#define CP_COMMIT() asm volatile("cp.async.commit_group;" ::: "memory")
#define CP_WAIT1()  asm volatile("cp.async.wait_group 1;" ::: "memory")
#define CP_WAIT2()  asm volatile("cp.async.wait_group 2;" ::: "memory")
#define CP_WAIT0()  asm volatile("cp.async.wait_group 0;" ::: "memory")

__device__ __forceinline__ void ldsm_x4(uint32_t& r0, uint32_t& r1, uint32_t& r2, uint32_t& r3,
                                        uint32_t addr) {
    asm volatile("ldmatrix.sync.aligned.m8n8.x4.shared.b16 {%0,%1,%2,%3}, [%4];"
                 : "=r"(r0), "=r"(r1), "=r"(r2), "=r"(r3) : "r"(addr));
}
__device__ __forceinline__ void ldsm_x4t(uint32_t& r0, uint32_t& r1, uint32_t& r2, uint32_t& r3,
                                         uint32_t addr) {
    asm volatile("ldmatrix.sync.aligned.m8n8.x4.trans.shared.b16 {%0,%1,%2,%3}, [%4];"
                 : "=r"(r0), "=r"(r1), "=r"(r2), "=r"(r3) : "r"(addr));
}
__device__ __forceinline__ void mma16816(float* d, const uint32_t* a, uint32_t b0, uint32_t b1) {
    asm volatile(
        "mma.sync.aligned.m16n8k16.row.col.f32.bf16.bf16.f32 "
        "{%0,%1,%2,%3}, {%4,%5,%6,%7}, {%8,%9}, {%0,%1,%2,%3};"
        : "+f"(d[0]), "+f"(d[1]), "+f"(d[2]), "+f"(d[3])
        : "r"(a[0]), "r"(a[1]), "r"(a[2]), "r"(a[3]), "r"(b0), "r"(b1));
}
__device__ __forceinline__ uint32_t packbf(float lo, float hi) {
    uint32_t r;
    asm("cvt.rn.bf16x2.f32 %0, %1, %2;" : "=r"(r) : "f"(hi), "f"(lo));
    return r;
}

// ------------------------- scratch (allocation-free) -------------------------
__device__ float g_qkv[NBS*THREE_D];
__device__ float g_attnproj[NBS*ND];
__device__ float g_x1[NBS*ND];
__device__ float g_Q[NHD*NHD];
__device__ float g_cos[NS*NHD];
__device__ float g_sin[NS*NHD];
__device__ float g_wqkv_rot[(size_t)ND*THREE_D];   // w_qkv with Q^T folded into q,k cols
// attention operands (bf16): q/k = [hi(64) | lo(64)] per token, v hi/lo planes
__device__ __nv_bfloat16 g_qa[(size_t)NB*NH*NS*128];
__device__ __nv_bfloat16 g_ka[(size_t)NB*NH*NS*128];
__device__ __nv_bfloat16 g_vh2[(size_t)NB*NH*NS*64];
__device__ __nv_bfloat16 g_vl2[(size_t)NB*NH*NS*64];
// split-bf16 activations: [M, 2K] = [hi | lo]  (third GEMM term wraps to hi)
__device__ __nv_bfloat16 g_h_aug[(size_t)NBS*2*ND];
__device__ __nv_bfloat16 g_attn_aug[(size_t)NBS*2*ND];
__device__ __nv_bfloat16 g_ap_aug[(size_t)NBS*2*ND];
__device__ __nv_bfloat16 g_h2_aug[(size_t)NBS*2*ND];
__device__ __nv_bfloat16 g_t_aug[(size_t)NBS*8*ND];
// augmented transposed weights: [N, 3K] = [hi | hi | lo]
__device__ __nv_bfloat16 g_wqkvT[3*ND*3*ND];
__device__ __nv_bfloat16 g_woutT[ND*3*ND];
__device__ __nv_bfloat16 g_wgateT[ND*3*ND];
__device__ __nv_bfloat16 g_wmgT[(size_t)8*ND*3*ND];   // column-permuted (g/val interleave)
__device__ __nv_bfloat16 g_wmoT[(size_t)ND*12*ND];

// ======================= split helpers ======================================
__device__ __forceinline__ void split_hi_lo(float v, __nv_bfloat16& hi, __nv_bfloat16& lo) {
    hi = __float2bfloat16(v);
    lo = __float2bfloat16(v - __bfloat162float(hi));
}
__device__ __forceinline__ void store_aug4(__nv_bfloat16* base, size_t rowbase, int K, int col,
                                           float v0, float v1, float v2, float v3) {
    __nv_bfloat16 h[4], l[4];
    split_hi_lo(v0, h[0], l[0]); split_hi_lo(v1, h[1], l[1]);
    split_hi_lo(v2, h[2], l[2]); split_hi_lo(v3, h[3], l[3]);
    __nv_bfloat162 p;
    p.x = h[0]; p.y = h[1]; *(__nv_bfloat162*)(base + rowbase + col) = p;
    p.x = h[2]; p.y = h[3]; *(__nv_bfloat162*)(base + rowbase + col + 2) = p;
    p.x = l[0]; p.y = l[1]; *(__nv_bfloat162*)(base + rowbase + K + col) = p;
    p.x = l[2]; p.y = l[3]; *(__nv_bfloat162*)(base + rowbase + K + col + 2) = p;
}
__device__ __forceinline__ void store_aug2(__nv_bfloat16* base, size_t rowbase, int K, int col,
                                           float v0, float v1) {
    __nv_bfloat16 h0, l0, h1, l1;
    split_hi_lo(v0, h0, l0); split_hi_lo(v1, h1, l1);
    __nv_bfloat162 p;
    p.x = h0; p.y = h1; *(__nv_bfloat162*)(base + rowbase + col) = p;
    p.x = l0; p.y = l1; *(__nv_bfloat162*)(base + rowbase + K + col) = p;
}

// ------------------------- rmsnorm -> split bf16 ----------------------------
__global__ __launch_bounds__(256)
void rmsnorm_split_kernel(const float* __restrict__ x, __nv_bfloat16* __restrict__ o) {
    int row = blockIdx.x;
    const float4* xr = (const float4*)(x + (size_t)row * ND);
    float4 v = xr[threadIdx.x];
    float ss = v.x*v.x + v.y*v.y + v.z*v.z + v.w*v.w;
    #pragma unroll
    for (int m = 16; m > 0; m >>= 1) ss += __shfl_xor_sync(0xffffffffu, ss, m);
    __shared__ float sred[8];
    if ((threadIdx.x & 31) == 0) sred[threadIdx.x >> 5] = ss;
    __syncthreads();
    float tot = 0.f;
    #pragma unroll
    for (int i = 0; i < 8; i++) tot += sred[i];
    float r = rsqrtf(tot * (1.0f / ND) + 1e-6f);
    store_aug4(o, (size_t)row * 2 * ND, ND, threadIdx.x * 4, v.x*r, v.y*r, v.z*r, v.w*r);
}

// ------------------- weight transpose + split (K,N)->(N,3K) -----------------
__device__ __forceinline__ void transpose_split_body(const float* __restrict__ B,
                                                     __nv_bfloat16* __restrict__ out,
                                                     int K, int N, int bx, int by) {
    __shared__ float sm[64][33];
    int k0 = bx * 64, n0 = by * 32;
    int tx = threadIdx.x, ty = threadIdx.y;
    int lin = ty * 32 + tx;
    #pragma unroll
    for (int e = 0; e < 2; e++) {
        int idx = lin + e * 1024;
        int kk = idx >> 5, nn = idx & 31;
        sm[kk][nn] = B[(size_t)(k0 + kk) * N + n0 + nn];
    }
    __syncthreads();
    int n = n0 + ty;
    int kk = 2 * tx;
    float v0 = sm[kk][ty], v1 = sm[kk + 1][ty];
    __nv_bfloat16 h0, l0, h1, l1;
    split_hi_lo(v0, h0, l0); split_hi_lo(v1, h1, l1);
    size_t base = (size_t)n * 3 * K;
    __nv_bfloat162 p;
    p.x = h0; p.y = h1;
    *(__nv_bfloat162*)(out + base + k0 + kk) = p;
    *(__nv_bfloat162*)(out + base + K + k0 + kk) = p;
    p.x = l0; p.y = l1;
    *(__nv_bfloat162*)(out + base + 2 * K + k0 + kk) = p;
}

__global__ __launch_bounds__(1024)
void transpose_split_kernel(const float* __restrict__ B, __nv_bfloat16* __restrict__ out,
                            int K, int N) {
    transpose_split_body(B, out, K, N, blockIdx.x, blockIdx.y);
}

// merged launch: w_out (512 blocks), w_gate (512), w_mlp_out (2048)
__global__ __launch_bounds__(1024)
void transpose_split_multi_kernel(const float* __restrict__ B0, __nv_bfloat16* __restrict__ o0,
                                  const float* __restrict__ B1, __nv_bfloat16* __restrict__ o1,
                                  const float* __restrict__ B2, __nv_bfloat16* __restrict__ o2) {
    int lin = blockIdx.x;
    if (lin < 512) {
        transpose_split_body(B0, o0, 1024, 1024, lin & 15, lin >> 4);
    } else if (lin < 1024) {
        int r = lin - 512;
        transpose_split_body(B1, o1, 1024, 1024, r & 15, r >> 4);
    } else {
        int r = lin - 1024;
        transpose_split_body(B2, o2, 4096, 1024, r & 63, r >> 6);
    }
}

// --- permuted variant for w_mlp_gate: out row n <- source col perm(n) -------
__global__ __launch_bounds__(1024)
void transpose_split_perm_kernel(const float* __restrict__ B, __nv_bfloat16* __restrict__ out,
                                 int K, int N) {
    __shared__ float sm[64][33];
    int k0 = blockIdx.x * 64, n0 = blockIdx.y * 32;
    int tx = threadIdx.x, ty = threadIdx.y;
    int lin = ty * 32 + tx;
    #pragma unroll
    for (int e = 0; e < 2; e++) {
        int idx = lin + e * 1024;
        int kk = idx >> 5, nn = idx & 31;
        int n = n0 + nn;
        int src = (n & 1) ? (n >> 1) + (N >> 1) : (n >> 1);
        sm[kk][nn] = B[(size_t)(k0 + kk) * N + src];
    }
    __syncthreads();
    int n = n0 + ty;
    int kk = 2 * tx;
    float v0 = sm[kk][ty], v1 = sm[kk + 1][ty];
    __nv_bfloat16 h0, l0, h1, l1;
    split_hi_lo(v0, h0, l0); split_hi_lo(v1, h1, l1);
    size_t base = (size_t)n * 3 * K;
    __nv_bfloat162 p;
    p.x = h0; p.y = h1;
    *(__nv_bfloat162*)(out + base + k0 + kk) = p;
    *(__nv_bfloat162*)(out + base + K + k0 + kk) = p;
    p.x = l0; p.y = l1;
    *(__nv_bfloat162*)(out + base + 2 * K + k0 + kk) = p;
}

// ----------------------- Householder Q (64x64) ------------------------------
__global__ void buildQ_kernel(const float* __restrict__ vs) {
    __shared__ float Qm[NHD][NHD];
    __shared__ float vv[NHD];
    int t = threadIdx.x;
    #pragma unroll
    for (int i = 0; i < NHD; i++) Qm[i][t] = (i == t) ? 1.f : 0.f;
    for (int r = 0; r < 32; r++) {
        __syncthreads();
        vv[t] = vs[r * NHD + t];
        __syncthreads();
        float w = 0.f, vn = 0.f;
        #pragma unroll
        for (int i = 0; i < NHD; i++) { w += vv[i] * Qm[i][t]; vn += vv[i] * vv[i]; }
        float c = 2.0f / (vn + 1e-8f);
        #pragma unroll
        for (int i = 0; i < NHD; i++) Qm[i][t] -= c * vv[i] * w;
    }
    __syncthreads();
    for (int i = 0; i < NHD; i++) g_Q[i * NHD + t] = Qm[i][t];
}

// ---- fold Q^T into q,k columns of w_qkv (smem-staged, conflict-free) -------
// W'[k, slot*64+j] = sum_d W[k, slot*64+d] * Q[j,d]  for slots 0..31 (q,k);
// v (slots 32..47) copied through.
__global__ __launch_bounds__(256)
void premul_qkv_kernel(const float* __restrict__ W, float* __restrict__ Wr) {
    __shared__ float Qs[64][65];
    __shared__ float wrow[2048];
    int tid = threadIdx.x;
    for (int i = tid; i < 4096; i += 256) Qs[i >> 6][i & 63] = g_Q[i];
    int row = blockIdx.x;
    const float* src = W + (size_t)row * THREE_D;
    for (int i = tid; i < 2048; i += 256) wrow[i] = src[i];
    float4 vv = ((const float4*)(src + 2048))[tid];
    __syncthreads();
    float* dst = Wr + (size_t)row * THREE_D;
    #pragma unroll
    for (int cc = 0; cc < 8; cc++) {
        int c = cc * 256 + tid;
        int slot = c >> 6, j = c & 63;
        const float* wr = wrow + slot * 64;
        float acc = 0.f;
        #pragma unroll 16
        for (int d = 0; d < 64; d++) acc += wr[d] * Qs[j][d];
        dst[c] = acc;
    }
    ((float4*)(dst + 2048))[tid] = vv;
}

// ----------------------------- rope tables ----------------------------------
__global__ void rope_tables_kernel() {
    int s = blockIdx.x;
    int d = threadIdx.x;
    int i = d & 31;
    float invf = powf(10000.0f, -(float)(2 * i) / 64.0f);
    float ang = (float)s * invf;
    g_cos[s * NHD + d] = cosf(ang);
    g_sin[s * NHD + d] = sinf(ang);
}

// --- RoPE (elementwise; rotation pre-folded into weights, post-rotation
//     cancels by orthogonality in QK^T) + head transpose + split bf16 --------
__global__ __launch_bounds__(256)
void rope_apply_kernel(const float* __restrict__ qkv) {
    int bs = blockIdx.x;
    int which = blockIdx.y;
    int b = bs >> 11, s = bs & 2047;
    int tid = threadIdx.x;
    int lane = tid & 63, grp = tid >> 6;

    if (which == 2) {
        #pragma unroll
        for (int hh = 0; hh < 4; hh++) {
            int h = grp * 4 + hh;
            int bh = b * NH + h;
            float v = qkv[(size_t)bs * THREE_D + 2 * ND + h * NHD + lane];
            __nv_bfloat16 hi, lo; split_hi_lo(v, hi, lo);
            size_t base = ((size_t)bh * NS + s) * 64 + lane;
            g_vh2[base] = hi;
            g_vl2[base] = lo;
        }
        return;
    }
    __shared__ float xb[4][2][NHD];
    float cs = g_cos[s * NHD + lane], sn = g_sin[s * NHD + lane];
    const float* src = qkv + (size_t)bs * THREE_D + which * ND;
    __nv_bfloat16* dst = (which == 0) ? g_qa : g_ka;
    const float qs = (which == 0) ? 0.125f : 1.0f;   // fold 1/sqrt(d) into q (exact pow2)
    #pragma unroll
    for (int hh = 0; hh < 4; hh++) {
        int h = grp * 4 + hh;
        int pb = hh & 1;
        xb[grp][pb][lane] = src[h * NHD + lane];
        __syncthreads();
        float val = xb[grp][pb][lane];
        float prt = xb[grp][pb][lane ^ 32];
        float rot = (lane < 32) ? -prt : prt;
        float o = (val * cs + rot * sn) * qs;
        int bh = b * NH + h;
        __nv_bfloat16 hi, lo; split_hi_lo(o, hi, lo);
        size_t base = ((size_t)bh * NS + s) * 128;
        dst[base + lane] = hi;
        dst[base + 64 + lane] = lo;
    }
}

// ==================== HMMA flash attention v2 ===============================
#define FQB 272                       // Q/K smem row stride bytes (136 bf16)
#define FVB 144                       // V smem row stride bytes (72 bf16)
#define FK_BYTES (64*FQB)             // 17408
#define FV_BYTES (64*FVB)             // 9216
#define FBUF (FK_BYTES + 2*FV_BYTES)  // 35840
#define FLS_SMEM (128*FQB + 2*FBUF)   // 106496

__global__ __launch_bounds__(256)
void flash_hmma_kernel() {
    extern __shared__ char smf[];
    const int qt = (NS / 128) - 1 - blockIdx.x;    // heavy tiles first
    const int bh = blockIdx.y;
    const int b = bh >> 4, hd = bh & 15;
    const int tid = threadIdx.x;
    const int w = tid >> 5, lane = tid & 31;
    const uint32_t sb = smem_u32(smf);
    const uint32_t sQ = sb;

    const __nv_bfloat16* qg = g_qa + ((size_t)bh * NS + (size_t)qt * 128) * 128;
    const __nv_bfloat16* kg = g_ka + (size_t)bh * NS * 128;
    const __nv_bfloat16* vhg = g_vh2 + (size_t)bh * NS * 64;
    const __nv_bfloat16* vlg = g_vl2 + (size_t)bh * NS * 64;

    #pragma unroll
    for (int i = 0; i < 8; i++) {
        int ch = tid + i * 256; int r = ch >> 4, c = ch & 15;
        cp_async16(sQ + r * FQB + c * 16, qg + (size_t)r * 128 + c * 8);
    }
    CP_COMMIT();

    auto load_kv = [&](int kt, int buf) {
        uint32_t sK = sb + 128 * FQB + buf * FBUF;
        uint32_t sVh = sK + FK_BYTES;
        uint32_t sVl = sVh + FV_BYTES;
        #pragma unroll
        for (int i = 0; i < 4; i++) {
            int ch = tid + i * 256; int r = ch >> 4, c = ch & 15;
            cp_async16(sK + r * FQB + c * 16, kg + (size_t)(kt * 64 + r) * 128 + c * 8);
        }
        #pragma unroll
        for (int i = 0; i < 2; i++) {
            int ch = tid + i * 256; int r = ch >> 3, c = ch & 7;
            cp_async16(sVh + r * FVB + c * 16, vhg + (size_t)(kt * 64 + r) * 64 + c * 8);
            cp_async16(sVl + r * FVB + c * 16, vlg + (size_t)(kt * 64 + r) * 64 + c * 8);
        }
        CP_COMMIT();
    };

    const int nkv = (qt + 1) * 2;
    load_kv(0, 0);
    CP_WAIT1();
    __syncthreads();

    const int a_r = lane & 15, a_c = (lane >> 4) * 8;
    uint32_t qf[8][4];
    #pragma unroll
    for (int ks = 0; ks < 8; ks++) {
        uint32_t addr = sQ + (uint32_t)((w * 16 + a_r) * FQB + (ks * 16 + a_c) * 2);
        ldsm_x4(qf[ks][0], qf[ks][1], qf[ks][2], qf[ks][3], addr);
    }

    float oacc[8][4];
    #pragma unroll
    for (int j = 0; j < 8; j++)
        #pragma unroll
        for (int e = 0; e < 4; e++) oacc[j][e] = 0.f;
    float mrow[2] = {-1e30f, -1e30f}, lrow[2] = {0.f, 0.f};

    const int b_g = lane >> 3, b_r2 = (b_g >> 1) * 8 + (lane & 7), b_c = (b_g & 1) * 8;
    const int vg = lane >> 3, vw = lane & 7;
    const int v_r = (vg & 1) * 8 + vw, v_c = (vg >> 1) * 8;

    for (int kt = 0; kt < nkv; kt++) {
        if (kt + 1 < nkv) { load_kv(kt + 1, (kt + 1) & 1); CP_WAIT1(); }
        else { CP_WAIT0(); }
        __syncthreads();
        uint32_t sK = sb + 128 * FQB + (kt & 1) * FBUF;
        uint32_t sVh = sK + FK_BYTES, sVl = sVh + FV_BYTES;

        float sacc[8][4];
        #pragma unroll
        for (int j = 0; j < 8; j++)
            #pragma unroll
            for (int e = 0; e < 4; e++) sacc[j][e] = 0.f;
        #pragma unroll
        for (int ks = 0; ks < 4; ks++) {
            uint32_t bfr[4][4];
            #pragma unroll
            for (int nb = 0; nb < 4; nb++) {
                uint32_t addr = sK + (uint32_t)((nb * 16 + b_r2) * FQB + (ks * 16 + b_c) * 2);
                ldsm_x4(bfr[nb][0], bfr[nb][1], bfr[nb][2], bfr[nb][3], addr);
            }
            #pragma unroll
            for (int j = 0; j < 8; j++) {
                mma16816(sacc[j], qf[ks],     bfr[j >> 1][(j & 1) * 2], bfr[j >> 1][(j & 1) * 2 + 1]);
                mma16816(sacc[j], qf[ks + 4], bfr[j >> 1][(j & 1) * 2], bfr[j >> 1][(j & 1) * 2 + 1]);
            }
        }
        #pragma unroll
        for (int ks = 0; ks < 4; ks++) {
            uint32_t bfr[4][4];
            #pragma unroll
            for (int nb = 0; nb < 4; nb++) {
                uint32_t addr = sK + (uint32_t)((nb * 16 + b_r2) * FQB + (64 + ks * 16 + b_c) * 2);
                ldsm_x4(bfr[nb][0], bfr[nb][1], bfr[nb][2], bfr[nb][3], addr);
            }
            #pragma unroll
            for (int j = 0; j < 8; j++)
                mma16816(sacc[j], qf[ks], bfr[j >> 1][(j & 1) * 2], bfr[j >> 1][(j & 1) * 2 + 1]);
        }

        // ---- online softmax (scale pre-folded into q) ----
        #pragma unroll
        for (int hf = 0; hf < 2; hf++) {
            float mt = -1e30f;
            #pragma unroll
            for (int j = 0; j < 8; j++)
                mt = fmaxf(mt, fmaxf(sacc[j][2*hf], sacc[j][2*hf+1]));
            mt = fmaxf(mt, __shfl_xor_sync(0xffffffffu, mt, 1));
            mt = fmaxf(mt, __shfl_xor_sync(0xffffffffu, mt, 2));
            float mn = fmaxf(mrow[hf], mt);
            float alpha = __expf(mrow[hf] - mn);
            mrow[hf] = mn;
            float lt = 0.f;
            #pragma unroll
            for (int j = 0; j < 8; j++) {
                float p0 = __expf(sacc[j][2*hf] - mn);
                float p1 = __expf(sacc[j][2*hf+1] - mn);
                sacc[j][2*hf] = p0; sacc[j][2*hf+1] = p1;
                lt += p0 + p1;
            }
            lt += __shfl_xor_sync(0xffffffffu, lt, 1);
            lt += __shfl_xor_sync(0xffffffffu, lt, 2);
            lrow[hf] = lrow[hf] * alpha + lt;
            #pragma unroll
            for (int j = 0; j < 8; j++) { oacc[j][2*hf] *= alpha; oacc[j][2*hf+1] *= alpha; }
        }

        uint32_t ahi[4][4], alo[4][4];
        #pragma unroll
        for (int kk = 0; kk < 4; kk++) {
            #pragma unroll
            for (int q = 0; q < 4; q++) {
                int j = 2 * kk + (q >> 1);
                float p0 = sacc[j][(q & 1) * 2], p1 = sacc[j][(q & 1) * 2 + 1];
                float h0 = __bfloat162float(__float2bfloat16(p0));
                float h1 = __bfloat162float(__float2bfloat16(p1));
                ahi[kk][q] = packbf(h0, h1);
                alo[kk][q] = packbf(p0 - h0, p1 - h1);
            }
        }

        #pragma unroll
        for (int kk = 0; kk < 4; kk++) {
            uint32_t bfh[4][4];
            #pragma unroll
            for (int nb = 0; nb < 4; nb++) {
                uint32_t addr = sVh + (uint32_t)((kk * 16 + v_r) * FVB + (nb * 16 + v_c) * 2);
                ldsm_x4t(bfh[nb][0], bfh[nb][1], bfh[nb][2], bfh[nb][3], addr);
            }
            #pragma unroll
            for (int j = 0; j < 8; j++) {
                mma16816(oacc[j], ahi[kk], bfh[j >> 1][(j & 1) * 2], bfh[j >> 1][(j & 1) * 2 + 1]);
                mma16816(oacc[j], alo[kk], bfh[j >> 1][(j & 1) * 2], bfh[j >> 1][(j & 1) * 2 + 1]);
            }
            uint32_t bfl[4][4];
            #pragma unroll
            for (int nb = 0; nb < 4; nb++) {
                uint32_t addr = sVl + (uint32_t)((kk * 16 + v_r) * FVB + (nb * 16 + v_c) * 2);
                ldsm_x4t(bfl[nb][0], bfl[nb][1], bfl[nb][2], bfl[nb][3], addr);
            }
            #pragma unroll
            for (int j = 0; j < 8; j++)
                mma16816(oacc[j], ahi[kk], bfl[j >> 1][(j & 1) * 2], bfl[j >> 1][(j & 1) * 2 + 1]);
        }
        __syncthreads();
    }

    float inv0 = 1.f / lrow[0], inv1 = 1.f / lrow[1];
    int r0 = qt * 128 + w * 16 + (lane >> 2);
    size_t row0 = (size_t)(b * NS + r0) * 2 * ND;
    size_t row1 = row0 + (size_t)8 * 2 * ND;
    #pragma unroll
    for (int j = 0; j < 8; j++) {
        int col = hd * 64 + j * 8 + (lane & 3) * 2;
        store_aug2(g_attn_aug, row0, ND, col, oacc[j][0] * inv0, oacc[j][1] * inv0);
        store_aug2(g_attn_aug, row1, ND, col, oacc[j][2] * inv1, oacc[j][3] * inv1);
    }
}

// ====================== HMMA bf16 GEMM (4-stage, A-wrap) ====================
#define HG_PAD    40
#define HG_STAGE  (2 * 128 * HG_PAD * 2)   // 20480
#define HG_SMEM   (4 * HG_STAGE)           // 81920

template<int EPI>
__global__ __launch_bounds__(256)
void hmma_gemm(const __nv_bfloat16* __restrict__ A, const __nv_bfloat16* __restrict__ Bt,
               float* __restrict__ C, int M, int N, int Kb,
               const float* __restrict__ bias,
               const float* __restrict__ e1, const float* __restrict__ e2)
{
    extern __shared__ char smc[];
    const int tid = threadIdx.x;
    const int wid = tid >> 5, lane = tid & 31;
    const int m0 = blockIdx.y * 128, n0 = blockIdx.x * 128;
    const int wm = (wid >> 2) * 64, wn = (wid & 3) * 32;
    const uint32_t sbase = smem_u32(smc);
    const int Kp = 3 * Kb;
    const int Ka = 2 * Kb;

    const int q0 = tid, q1 = tid + 256;
    const int ra0 = q0 >> 2, ca0 = (q0 & 3);
    const int ra1 = q1 >> 2, ca1 = (q1 & 3);

    auto load_stage = [&](int s, int kk) {
        int kka = (kk >= Ka) ? kk - Ka : kk;
        uint32_t aS = sbase + s * HG_STAGE;
        uint32_t bS = aS + 128 * HG_PAD * 2;
        cp_async16(aS + ra0 * 80 + ca0 * 16, A + (size_t)(m0 + ra0) * Ka + kka + ca0 * 8);
        cp_async16(aS + ra1 * 80 + ca1 * 16, A + (size_t)(m0 + ra1) * Ka + kka + ca1 * 8);
        cp_async16(bS + ra0 * 80 + ca0 * 16, Bt + (size_t)(n0 + ra0) * Kp + kk + ca0 * 8);
        cp_async16(bS + ra1 * 80 + ca1 * 16, Bt + (size_t)(n0 + ra1) * Kp + kk + ca1 * 8);
        CP_COMMIT();
    };

    const int KT = Kp >> 5;
    load_stage(0, 0);
    load_stage(1, 32);
    load_stage(2, 64);

    float acc[16][4];
    #pragma unroll
    for (int f = 0; f < 16; f++)
        #pragma unroll
        for (int e = 0; e < 4; e++) acc[f][e] = 0.f;

    const int a_r = (lane & 15);
    const int a_c = (lane >> 4) * 8;
    const int b_g = lane >> 3;
    const int b_r = (b_g >> 1) * 8 + (lane & 7);
    const int b_c = (b_g & 1) * 8;

    for (int kt = 0; kt < KT; kt++) {
        CP_WAIT2();
        __syncthreads();
        if (kt + 3 < KT) load_stage((kt + 3) & 3, (kt + 3) * 32);

        uint32_t aS = sbase + (kt & 3) * HG_STAGE;
        uint32_t bS = aS + 128 * HG_PAD * 2;

        #pragma unroll
        for (int ks = 0; ks < 2; ks++) {
            uint32_t af[4][4];
            #pragma unroll
            for (int mf = 0; mf < 4; mf++) {
                uint32_t addr = aS + (uint32_t)((wm + mf * 16 + a_r) * 80 + (ks * 16 + a_c) * 2);
                ldsm_x4(af[mf][0], af[mf][1], af[mf][2], af[mf][3], addr);
            }
            uint32_t bfr[2][4];
            #pragma unroll
            for (int nb = 0; nb < 2; nb++) {
                uint32_t addr = bS + (uint32_t)((wn + nb * 16 + b_r) * 80 + (ks * 16 + b_c) * 2);
                ldsm_x4(bfr[nb][0], bfr[nb][1], bfr[nb][2], bfr[nb][3], addr);
            }
            #pragma unroll
            for (int mf = 0; mf < 4; mf++)
                #pragma unroll
                for (int nf = 0; nf < 4; nf++) {
                    int nb = nf >> 1, pr = (nf & 1) * 2;
                    mma16816(acc[mf * 4 + nf], af[mf], bfr[nb][pr], bfr[nb][pr + 1]);
                }
        }
    }

    #pragma unroll
    for (int mf = 0; mf < 4; mf++) {
        #pragma unroll
        for (int nf = 0; nf < 4; nf++) {
            float* a = acc[mf * 4 + nf];
            int col = n0 + wn + nf * 8 + (lane & 3) * 2;
            #pragma unroll
            for (int half = 0; half < 2; half++) {
                int row = m0 + wm + mf * 16 + (lane >> 2) + half * 8;
                size_t idx = (size_t)row * N + col;
                float v0 = a[half * 2], v1 = a[half * 2 + 1];
                if (EPI == 0) {
                    if (bias) { v0 += bias[col]; v1 += bias[col + 1]; }
                    *(float2*)(C + idx) = make_float2(v0, v1);
                } else if (EPI == 1) {
                    float g0 = 1.f / (1.f + __expf(-(v0 + bias[col])));
                    float g1 = 1.f / (1.f + __expf(-(v1 + bias[col + 1])));
                    float2 ee1 = *(const float2*)(e1 + idx);
                    float2 ee2 = *(const float2*)(e2 + idx);
                    *(float2*)(C + idx) = make_float2(ee2.x + ee1.x * g0, ee2.y + ee1.y * g1);
                } else if (EPI == 2) {
                    float2 ee2 = *(const float2*)(e2 + idx);
                    *(float2*)(C + idx) = make_float2(ee2.x + v0 + bias[col],
                                                      ee2.y + v1 + bias[col + 1]);
                } else if (EPI == 3) {
                    *(float2*)(C + idx) = make_float2(v0, v1);
                    __nv_bfloat16* Ca = (__nv_bfloat16*)(uintptr_t)e1;
                    store_aug2(Ca, (size_t)row * 2 * N, N, col, v0, v1);
                } else {
                    int j = col >> 1;
                    float g = v0 + bias[j];
                    float vv = v1 + bias[j + (N >> 1)];
                    float t = vv * (0.5f * g * (1.f + erff(g * 0.70710678118654752f)));
                    __nv_bfloat16 hi, lo; split_hi_lo(t, hi, lo);
                    __nv_bfloat16* T = (__nv_bfloat16*)(uintptr_t)e1;
                    size_t rb = (size_t)row * N;
                    T[rb + j] = hi;
                    T[rb + (N >> 1) + j] = lo;
                }
            }
        }
    }
}

// --------------------------------- launcher ---------------------------------
extern "C" void kernel_launch(void* const* d_in, const int* in_sizes, int n_in,
                              void* d_out, int out_size) {
    const float* x          = (const float*)d_in[0];
    const float* vs         = (const float*)d_in[3];
    const float* w_qkv      = (const float*)d_in[4];
    const float* w_out      = (const float*)d_in[5];
    const float* w_gate     = (const float*)d_in[6];
    const float* b_gate     = (const float*)d_in[7];
    const float* w_mlp_gate = (const float*)d_in[8];
    const float* b_mlp_gate = (const float*)d_in[9];
    const float* w_mlp_out  = (const float*)d_in[10];
    const float* b_mlp_out  = (const float*)d_in[11];
    float* out = (float*)d_out;

    float *p_qkv, *p_attnproj, *p_x1, *p_wrot;
    __nv_bfloat16 *p_h_aug, *p_attn_aug, *p_ap_aug, *p_h2_aug, *p_t_aug;
    __nv_bfloat16 *p_wqkvT, *p_woutT, *p_wgateT, *p_wmgT, *p_wmoT;
    cudaGetSymbolAddress((void**)&p_qkv, g_qkv);
    cudaGetSymbolAddress((void**)&p_attnproj, g_attnproj);
    cudaGetSymbolAddress((void**)&p_x1, g_x1);
    cudaGetSymbolAddress((void**)&p_wrot, g_wqkv_rot);
    cudaGetSymbolAddress((void**)&p_h_aug, g_h_aug);
    cudaGetSymbolAddress((void**)&p_attn_aug, g_attn_aug);
    cudaGetSymbolAddress((void**)&p_ap_aug, g_ap_aug);
    cudaGetSymbolAddress((void**)&p_h2_aug, g_h2_aug);
    cudaGetSymbolAddress((void**)&p_t_aug, g_t_aug);
    cudaGetSymbolAddress((void**)&p_wqkvT, g_wqkvT);
    cudaGetSymbolAddress((void**)&p_woutT, g_woutT);
    cudaGetSymbolAddress((void**)&p_wgateT, g_wgateT);
    cudaGetSymbolAddress((void**)&p_wmgT, g_wmgT);
    cudaGetSymbolAddress((void**)&p_wmoT, g_wmoT);

    cudaFuncSetAttribute(flash_hmma_kernel, cudaFuncAttributeMaxDynamicSharedMemorySize, FLS_SMEM);
    cudaFuncSetAttribute(hmma_gemm<0>, cudaFuncAttributeMaxDynamicSharedMemorySize, HG_SMEM);
    cudaFuncSetAttribute(hmma_gemm<1>, cudaFuncAttributeMaxDynamicSharedMemorySize, HG_SMEM);
    cudaFuncSetAttribute(hmma_gemm<2>, cudaFuncAttributeMaxDynamicSharedMemorySize, HG_SMEM);
    cudaFuncSetAttribute(hmma_gemm<3>, cudaFuncAttributeMaxDynamicSharedMemorySize, HG_SMEM);
    cudaFuncSetAttribute(hmma_gemm<4>, cudaFuncAttributeMaxDynamicSharedMemorySize, HG_SMEM);

    dim3 t32(32, 32);
    // Q build + fold Q^T into q,k weight columns (smem-staged premul)
    buildQ_kernel<<<1, 64>>>(vs);
    premul_qkv_kernel<<<ND, 256>>>(w_qkv, p_wrot);
    transpose_split_kernel<<<dim3(ND/64, THREE_D/32), t32>>>(p_wrot, p_wqkvT, ND, THREE_D);
    transpose_split_multi_kernel<<<3072, t32>>>(w_out, p_woutT, w_gate, p_wgateT,
                                                w_mlp_out, p_wmoT);
    transpose_split_perm_kernel<<<dim3(ND/64, 8*ND/32), t32>>>(w_mlp_gate, p_wmgT, ND, 8*ND);
    rope_tables_kernel<<<NS, 64>>>();

    // 1. h = split(rmsnorm(x))  [hi|lo]
    rmsnorm_split_kernel<<<NBS, 256>>>(x, p_h_aug);
    // 2. qkv = h @ w_qkv_rot  (q,k already rotated)
    hmma_gemm<0><<<dim3(THREE_D/128, NBS/128), 256, HG_SMEM>>>(
        p_h_aug, p_wqkvT, p_qkv, NBS, THREE_D, ND, nullptr, nullptr, nullptr);
    // 3. elementwise RoPE + head transpose -> split bf16 operands (q pre-scaled)
    rope_apply_kernel<<<dim3(NBS, 3), 256>>>(p_qkv);
    // 4. attention (HMMA) -> attn [hi|lo]  (post-rotation cancels in QK^T)
    flash_hmma_kernel<<<dim3(NS/128, NB*NH), 256, FLS_SMEM>>>();
    // 5. attnproj = attn @ w_out  (+ fused [hi|lo] split)
    hmma_gemm<3><<<dim3(ND/128, NBS/128), 256, HG_SMEM>>>(
        p_attn_aug, p_woutT, p_attnproj, NBS, ND, ND, nullptr,
        (const float*)p_ap_aug, nullptr);
    // 6. x1 = x + attnproj * sigmoid(attnproj @ w_gate + b_gate)
    hmma_gemm<1><<<dim3(ND/128, NBS/128), 256, HG_SMEM>>>(
        p_ap_aug, p_wgateT, p_x1, NBS, ND, ND, b_gate, p_attnproj, x);
    // 7. h2 = split(rmsnorm(x1))
    rmsnorm_split_kernel<<<NBS, 256>>>(p_x1, p_h2_aug);
    // 8. fused mlp_gate GEMM + GLU -> t [hi|lo]   (permuted weights)
    hmma_gemm<4><<<dim3(8*ND/128, NBS/128), 256, HG_SMEM>>>(
        p_h2_aug, p_wmgT, p_x1 /*unused*/, NBS, 8*ND, ND, b_mlp_gate,
        (const float*)p_t_aug, nullptr);
    // 9. out = x1 + t @ w_mlp_out + b
    hmma_gemm<2><<<dim3(ND/128, NBS/128), 256, HG_SMEM>>>(
        p_t_aug, p_wmoT, out, NBS, ND, 4*ND, b_mlp_out, nullptr, p_x1);
}

// round 16
// speedup vs baseline: 1.2275x; 1.0004x over previous
#include <cuda_runtime.h>
#include <cuda_bf16.h>
#include <cstdint>
#include <math.h>

#define NB 2
#define NS 2048
#define ND 1024
#define NH 16
#define NHD 64
#define NBS (NB*NS)        // 4096
#define THREE_D (3*ND)     // 3072

// ===================== helpers ==============================================
__device__ __forceinline__ uint32_t smem_u32(const void* p) {
    uint32_t a;
    asm("{ .reg .u64 t; cvta.to.shared.u64 t, %1; cvt.u32.u64 %0, t; }" : "=r"(a) : "l"(p));
    return a;
}
__device__ __forceinline__ void cp_async16(uint32_t s, const void* g) {
    asm volatile("cp.async.cg.shared.global [%0], [%1], 16;" :: "r"(s), "l"(g));
}
#define CP_COMMIT() asm volatile("cp.async.commit_group;" ::: "memory")
#define CP_WAIT1()  asm volatile("cp.async.wait_group 1;" ::: "memory")
#define CP_WAIT2()  asm volatile("cp.async.wait_group 2;" ::: "memory")
#define CP_WAIT0()  asm volatile("cp.async.wait_group 0;" ::: "memory")

__device__ __forceinline__ void ldsm_x4(uint32_t& r0, uint32_t& r1, uint32_t& r2, uint32_t& r3,
                                        uint32_t addr) {
    asm volatile("ldmatrix.sync.aligned.m8n8.x4.shared.b16 {%0,%1,%2,%3}, [%4];"
                 : "=r"(r0), "=r"(r1), "=r"(r2), "=r"(r3) : "r"(addr));
}
__device__ __forceinline__ void ldsm_x4t(uint32_t& r0, uint32_t& r1, uint32_t& r2, uint32_t& r3,
                                         uint32_t addr) {
    asm volatile("ldmatrix.sync.aligned.m8n8.x4.trans.shared.b16 {%0,%1,%2,%3}, [%4];"
                 : "=r"(r0), "=r"(r1), "=r"(r2), "=r"(r3) : "r"(addr));
}
__device__ __forceinline__ void mma16816(float* d, const uint32_t* a, uint32_t b0, uint32_t b1) {
    asm volatile(
        "mma.sync.aligned.m16n8k16.row.col.f32.bf16.bf16.f32 "
        "{%0,%1,%2,%3}, {%4,%5,%6,%7}, {%8,%9}, {%0,%1,%2,%3};"
        : "+f"(d[0]), "+f"(d[1]), "+f"(d[2]), "+f"(d[3])
        : "r"(a[0]), "r"(a[1]), "r"(a[2]), "r"(a[3]), "r"(b0), "r"(b1));
}
__device__ __forceinline__ uint32_t packbf(float lo, float hi) {
    uint32_t r;
    asm("cvt.rn.bf16x2.f32 %0, %1, %2;" : "=r"(r) : "f"(hi), "f"(lo));
    return r;
}

// ------------------------- scratch (allocation-free) -------------------------
__device__ float g_qkv[NBS*THREE_D];
__device__ float g_attnproj[NBS*ND];
__device__ float g_x1[NBS*ND];
__device__ float g_Q[NHD*NHD];
__device__ float g_cos[NS*NHD];
__device__ float g_sin[NS*NHD];
__device__ float g_wqkv_rot[(size_t)ND*THREE_D];   // w_qkv with Q^T folded into q,k cols
// attention operands (bf16): q/k = [hi(64) | lo(64)] per token, v hi/lo planes
__device__ __nv_bfloat16 g_qa[(size_t)NB*NH*NS*128];
__device__ __nv_bfloat16 g_ka[(size_t)NB*NH*NS*128];
__device__ __nv_bfloat16 g_vh2[(size_t)NB*NH*NS*64];
__device__ __nv_bfloat16 g_vl2[(size_t)NB*NH*NS*64];
// split-bf16 activations: [M, 2K] = [hi | lo]  (third GEMM term wraps to hi)
__device__ __nv_bfloat16 g_h_aug[(size_t)NBS*2*ND];
__device__ __nv_bfloat16 g_attn_aug[(size_t)NBS*2*ND];
__device__ __nv_bfloat16 g_ap_aug[(size_t)NBS*2*ND];
__device__ __nv_bfloat16 g_h2_aug[(size_t)NBS*2*ND];
__device__ __nv_bfloat16 g_t_aug[(size_t)NBS*8*ND];
// augmented transposed weights: [N, 3K] = [hi | hi | lo]
__device__ __nv_bfloat16 g_wqkvT[3*ND*3*ND];
__device__ __nv_bfloat16 g_woutT[ND*3*ND];
__device__ __nv_bfloat16 g_wgateT[ND*3*ND];
__device__ __nv_bfloat16 g_wmgT[(size_t)8*ND*3*ND];   // column-permuted (g/val interleave)
__device__ __nv_bfloat16 g_wmoT[(size_t)ND*12*ND];

// ======================= split helpers ======================================
__device__ __forceinline__ void split_hi_lo(float v, __nv_bfloat16& hi, __nv_bfloat16& lo) {
    hi = __float2bfloat16(v);
    lo = __float2bfloat16(v - __bfloat162float(hi));
}
__device__ __forceinline__ void store_aug4(__nv_bfloat16* base, size_t rowbase, int K, int col,
                                           float v0, float v1, float v2, float v3) {
    __nv_bfloat16 h[4], l[4];
    split_hi_lo(v0, h[0], l[0]); split_hi_lo(v1, h[1], l[1]);
    split_hi_lo(v2, h[2], l[2]); split_hi_lo(v3, h[3], l[3]);
    __nv_bfloat162 p;
    p.x = h[0]; p.y = h[1]; *(__nv_bfloat162*)(base + rowbase + col) = p;
    p.x = h[2]; p.y = h[3]; *(__nv_bfloat162*)(base + rowbase + col + 2) = p;
    p.x = l[0]; p.y = l[1]; *(__nv_bfloat162*)(base + rowbase + K + col) = p;
    p.x = l[2]; p.y = l[3]; *(__nv_bfloat162*)(base + rowbase + K + col + 2) = p;
}
__device__ __forceinline__ void store_aug2(__nv_bfloat16* base, size_t rowbase, int K, int col,
                                           float v0, float v1) {
    __nv_bfloat16 h0, l0, h1, l1;
    split_hi_lo(v0, h0, l0); split_hi_lo(v1, h1, l1);
    __nv_bfloat162 p;
    p.x = h0; p.y = h1; *(__nv_bfloat162*)(base + rowbase + col) = p;
    p.x = l0; p.y = l1; *(__nv_bfloat162*)(base + rowbase + K + col) = p;
}

// ------------------------- rmsnorm -> split bf16 ----------------------------
__global__ __launch_bounds__(256)
void rmsnorm_split_kernel(const float* __restrict__ x, __nv_bfloat16* __restrict__ o) {
    int row = blockIdx.x;
    const float4* xr = (const float4*)(x + (size_t)row * ND);
    float4 v = xr[threadIdx.x];
    float ss = v.x*v.x + v.y*v.y + v.z*v.z + v.w*v.w;
    #pragma unroll
    for (int m = 16; m > 0; m >>= 1) ss += __shfl_xor_sync(0xffffffffu, ss, m);
    __shared__ float sred[8];
    if ((threadIdx.x & 31) == 0) sred[threadIdx.x >> 5] = ss;
    __syncthreads();
    float tot = 0.f;
    #pragma unroll
    for (int i = 0; i < 8; i++) tot += sred[i];
    float r = rsqrtf(tot * (1.0f / ND) + 1e-6f);
    store_aug4(o, (size_t)row * 2 * ND, ND, threadIdx.x * 4, v.x*r, v.y*r, v.z*r, v.w*r);
}

// ------------------- weight transpose + split (K,N)->(N,3K) -----------------
__device__ __forceinline__ void transpose_split_body(const float* __restrict__ B,
                                                     __nv_bfloat16* __restrict__ out,
                                                     int K, int N, int bx, int by) {
    __shared__ float sm[64][33];
    int k0 = bx * 64, n0 = by * 32;
    int tx = threadIdx.x, ty = threadIdx.y;
    int lin = ty * 32 + tx;
    #pragma unroll
    for (int e = 0; e < 2; e++) {
        int idx = lin + e * 1024;
        int kk = idx >> 5, nn = idx & 31;
        sm[kk][nn] = B[(size_t)(k0 + kk) * N + n0 + nn];
    }
    __syncthreads();
    int n = n0 + ty;
    int kk = 2 * tx;
    float v0 = sm[kk][ty], v1 = sm[kk + 1][ty];
    __nv_bfloat16 h0, l0, h1, l1;
    split_hi_lo(v0, h0, l0); split_hi_lo(v1, h1, l1);
    size_t base = (size_t)n * 3 * K;
    __nv_bfloat162 p;
    p.x = h0; p.y = h1;
    *(__nv_bfloat162*)(out + base + k0 + kk) = p;
    *(__nv_bfloat162*)(out + base + K + k0 + kk) = p;
    p.x = l0; p.y = l1;
    *(__nv_bfloat162*)(out + base + 2 * K + k0 + kk) = p;
}

// merged launch: w_qkv_rot (1536), w_out (512), w_gate (512), w_mlp_out (2048)
__global__ __launch_bounds__(1024)
void transpose_split_multi_kernel(const float* __restrict__ Bq, __nv_bfloat16* __restrict__ oq,
                                  const float* __restrict__ B0, __nv_bfloat16* __restrict__ o0,
                                  const float* __restrict__ B1, __nv_bfloat16* __restrict__ o1,
                                  const float* __restrict__ B2, __nv_bfloat16* __restrict__ o2) {
    int lin = blockIdx.x;
    if (lin < 1536) {
        transpose_split_body(Bq, oq, 1024, 3072, lin & 15, lin >> 4);
    } else if (lin < 2048) {
        int r = lin - 1536;
        transpose_split_body(B0, o0, 1024, 1024, r & 15, r >> 4);
    } else if (lin < 2560) {
        int r = lin - 2048;
        transpose_split_body(B1, o1, 1024, 1024, r & 15, r >> 4);
    } else {
        int r = lin - 2560;
        transpose_split_body(B2, o2, 4096, 1024, r & 63, r >> 6);
    }
}

// --- permuted variant for w_mlp_gate: out row n <- source col perm(n) -------
__global__ __launch_bounds__(1024)
void transpose_split_perm_kernel(const float* __restrict__ B, __nv_bfloat16* __restrict__ out,
                                 int K, int N) {
    __shared__ float sm[64][33];
    int k0 = blockIdx.x * 64, n0 = blockIdx.y * 32;
    int tx = threadIdx.x, ty = threadIdx.y;
    int lin = ty * 32 + tx;
    #pragma unroll
    for (int e = 0; e < 2; e++) {
        int idx = lin + e * 1024;
        int kk = idx >> 5, nn = idx & 31;
        int n = n0 + nn;
        int src = (n & 1) ? (n >> 1) + (N >> 1) : (n >> 1);
        sm[kk][nn] = B[(size_t)(k0 + kk) * N + src];
    }
    __syncthreads();
    int n = n0 + ty;
    int kk = 2 * tx;
    float v0 = sm[kk][ty], v1 = sm[kk + 1][ty];
    __nv_bfloat16 h0, l0, h1, l1;
    split_hi_lo(v0, h0, l0); split_hi_lo(v1, h1, l1);
    size_t base = (size_t)n * 3 * K;
    __nv_bfloat162 p;
    p.x = h0; p.y = h1;
    *(__nv_bfloat162*)(out + base + k0 + kk) = p;
    *(__nv_bfloat162*)(out + base + K + k0 + kk) = p;
    p.x = l0; p.y = l1;
    *(__nv_bfloat162*)(out + base + 2 * K + k0 + kk) = p;
}

// ----------------------- Householder Q (64x64) ------------------------------
__global__ void buildQ_kernel(const float* __restrict__ vs) {
    __shared__ float Qm[NHD][NHD];
    __shared__ float vv[NHD];
    int t = threadIdx.x;
    #pragma unroll
    for (int i = 0; i < NHD; i++) Qm[i][t] = (i == t) ? 1.f : 0.f;
    for (int r = 0; r < 32; r++) {
        __syncthreads();
        vv[t] = vs[r * NHD + t];
        __syncthreads();
        float w = 0.f, vn = 0.f;
        #pragma unroll
        for (int i = 0; i < NHD; i++) { w += vv[i] * Qm[i][t]; vn += vv[i] * vv[i]; }
        float c = 2.0f / (vn + 1e-8f);
        #pragma unroll
        for (int i = 0; i < NHD; i++) Qm[i][t] -= c * vv[i] * w;
    }
    __syncthreads();
    for (int i = 0; i < NHD; i++) g_Q[i * NHD + t] = Qm[i][t];
}

// ---- fold Q^T into q,k columns of w_qkv (smem-staged, conflict-free) -------
__global__ __launch_bounds__(256)
void premul_qkv_kernel(const float* __restrict__ W, float* __restrict__ Wr) {
    __shared__ float Qs[64][65];
    __shared__ float wrow[2048];
    int tid = threadIdx.x;
    for (int i = tid; i < 4096; i += 256) Qs[i >> 6][i & 63] = g_Q[i];
    int row = blockIdx.x;
    const float* src = W + (size_t)row * THREE_D;
    for (int i = tid; i < 2048; i += 256) wrow[i] = src[i];
    float4 vv = ((const float4*)(src + 2048))[tid];
    __syncthreads();
    float* dst = Wr + (size_t)row * THREE_D;
    #pragma unroll
    for (int cc = 0; cc < 8; cc++) {
        int c = cc * 256 + tid;
        int slot = c >> 6, j = c & 63;
        const float* wr = wrow + slot * 64;
        float acc = 0.f;
        #pragma unroll 16
        for (int d = 0; d < 64; d++) acc += wr[d] * Qs[j][d];
        dst[c] = acc;
    }
    ((float4*)(dst + 2048))[tid] = vv;
}

// ----------------------------- rope tables ----------------------------------
__global__ void rope_tables_kernel() {
    int s = blockIdx.x;
    int d = threadIdx.x;
    int i = d & 31;
    float invf = powf(10000.0f, -(float)(2 * i) / 64.0f);
    float ang = (float)s * invf;
    g_cos[s * NHD + d] = cosf(ang);
    g_sin[s * NHD + d] = sinf(ang);
}

// --- RoPE (in-thread pair; rotation folded into weights) + split bf16 -------
// lane l owns dims (l, l+32) of a head -> rotate_half partner is thread-local.
__global__ __launch_bounds__(256)
void rope_apply_kernel(const float* __restrict__ qkv) {
    int bs = blockIdx.x;
    int b = bs >> 11, s = bs & 2047;
    int w = threadIdx.x >> 5, l = threadIdx.x & 31;
    float cs0 = g_cos[s * NHD + l],      sn0 = g_sin[s * NHD + l];
    float cs1 = g_cos[s * NHD + 32 + l], sn1 = g_sin[s * NHD + 32 + l];
    const float* base = qkv + (size_t)bs * THREE_D;
    #pragma unroll
    for (int hh = 0; hh < 2; hh++) {
        int h = w + hh * 8;
        int bh = b * NH + h;
        // q (scale 1/8 folded in, exact pow2)
        {
            float q0 = base[h * 64 + l], q1 = base[h * 64 + 32 + l];
            float o0 = (q0 * cs0 - q1 * sn0) * 0.125f;
            float o1 = (q1 * cs1 + q0 * sn1) * 0.125f;
            __nv_bfloat16 h0, l0, h1, l1;
            split_hi_lo(o0, h0, l0); split_hi_lo(o1, h1, l1);
            size_t db = ((size_t)bh * NS + s) * 128;
            g_qa[db + l] = h0;      g_qa[db + 32 + l] = h1;
            g_qa[db + 64 + l] = l0; g_qa[db + 96 + l] = l1;
        }
        // k
        {
            float k0 = base[ND + h * 64 + l], k1 = base[ND + h * 64 + 32 + l];
            float o0 = k0 * cs0 - k1 * sn0;
            float o1 = k1 * cs1 + k0 * sn1;
            __nv_bfloat16 h0, l0, h1, l1;
            split_hi_lo(o0, h0, l0); split_hi_lo(o1, h1, l1);
            size_t db = ((size_t)bh * NS + s) * 128;
            g_ka[db + l] = h0;      g_ka[db + 32 + l] = h1;
            g_ka[db + 64 + l] = l0; g_ka[db + 96 + l] = l1;
        }
        // v (hi/lo planes)
        {
            float v0 = base[2 * ND + h * 64 + l], v1 = base[2 * ND + h * 64 + 32 + l];
            __nv_bfloat16 h0, l0, h1, l1;
            split_hi_lo(v0, h0, l0); split_hi_lo(v1, h1, l1);
            size_t db = ((size_t)bh * NS + s) * 64;
            g_vh2[db + l] = h0; g_vh2[db + 32 + l] = h1;
            g_vl2[db + l] = l0; g_vl2[db + 32 + l] = l1;
        }
    }
}

// ==================== HMMA flash attention v2 ===============================
#define FQB 272                       // Q/K smem row stride bytes (136 bf16)
#define FVB 144                       // V smem row stride bytes (72 bf16)
#define FK_BYTES (64*FQB)             // 17408
#define FV_BYTES (64*FVB)             // 9216
#define FBUF (FK_BYTES + 2*FV_BYTES)  // 35840
#define FLS_SMEM (128*FQB + 2*FBUF)   // 106496

__global__ __launch_bounds__(256)
void flash_hmma_kernel() {
    extern __shared__ char smf[];
    const int qt = (NS / 128) - 1 - blockIdx.x;    // heavy tiles first
    const int bh = blockIdx.y;
    const int b = bh >> 4, hd = bh & 15;
    const int tid = threadIdx.x;
    const int w = tid >> 5, lane = tid & 31;
    const uint32_t sb = smem_u32(smf);
    const uint32_t sQ = sb;

    const __nv_bfloat16* qg = g_qa + ((size_t)bh * NS + (size_t)qt * 128) * 128;
    const __nv_bfloat16* kg = g_ka + (size_t)bh * NS * 128;
    const __nv_bfloat16* vhg = g_vh2 + (size_t)bh * NS * 64;
    const __nv_bfloat16* vlg = g_vl2 + (size_t)bh * NS * 64;

    #pragma unroll
    for (int i = 0; i < 8; i++) {
        int ch = tid + i * 256; int r = ch >> 4, c = ch & 15;
        cp_async16(sQ + r * FQB + c * 16, qg + (size_t)r * 128 + c * 8);
    }
    CP_COMMIT();

    auto load_kv = [&](int kt, int buf) {
        uint32_t sK = sb + 128 * FQB + buf * FBUF;
        uint32_t sVh = sK + FK_BYTES;
        uint32_t sVl = sVh + FV_BYTES;
        #pragma unroll
        for (int i = 0; i < 4; i++) {
            int ch = tid + i * 256; int r = ch >> 4, c = ch & 15;
            cp_async16(sK + r * FQB + c * 16, kg + (size_t)(kt * 64 + r) * 128 + c * 8);
        }
        #pragma unroll
        for (int i = 0; i < 2; i++) {
            int ch = tid + i * 256; int r = ch >> 3, c = ch & 7;
            cp_async16(sVh + r * FVB + c * 16, vhg + (size_t)(kt * 64 + r) * 64 + c * 8);
            cp_async16(sVl + r * FVB + c * 16, vlg + (size_t)(kt * 64 + r) * 64 + c * 8);
        }
        CP_COMMIT();
    };

    const int nkv = (qt + 1) * 2;
    load_kv(0, 0);
    CP_WAIT1();
    __syncthreads();

    const int a_r = lane & 15, a_c = (lane >> 4) * 8;
    uint32_t qf[8][4];
    #pragma unroll
    for (int ks = 0; ks < 8; ks++) {
        uint32_t addr = sQ + (uint32_t)((w * 16 + a_r) * FQB + (ks * 16 + a_c) * 2);
        ldsm_x4(qf[ks][0], qf[ks][1], qf[ks][2], qf[ks][3], addr);
    }

    float oacc[8][4];
    #pragma unroll
    for (int j = 0; j < 8; j++)
        #pragma unroll
        for (int e = 0; e < 4; e++) oacc[j][e] = 0.f;
    float mrow[2] = {-1e30f, -1e30f}, lrow[2] = {0.f, 0.f};

    const int b_g = lane >> 3, b_r2 = (b_g >> 1) * 8 + (lane & 7), b_c = (b_g & 1) * 8;
    const int vg = lane >> 3, vw = lane & 7;
    const int v_r = (vg & 1) * 8 + vw, v_c = (vg >> 1) * 8;

    for (int kt = 0; kt < nkv; kt++) {
        if (kt + 1 < nkv) { load_kv(kt + 1, (kt + 1) & 1); CP_WAIT1(); }
        else { CP_WAIT0(); }
        __syncthreads();
        uint32_t sK = sb + 128 * FQB + (kt & 1) * FBUF;
        uint32_t sVh = sK + FK_BYTES, sVl = sVh + FV_BYTES;

        float sacc[8][4];
        #pragma unroll
        for (int j = 0; j < 8; j++)
            #pragma unroll
            for (int e = 0; e < 4; e++) sacc[j][e] = 0.f;
        #pragma unroll
        for (int ks = 0; ks < 4; ks++) {
            uint32_t bfr[4][4];
            #pragma unroll
            for (int nb = 0; nb < 4; nb++) {
                uint32_t addr = sK + (uint32_t)((nb * 16 + b_r2) * FQB + (ks * 16 + b_c) * 2);
                ldsm_x4(bfr[nb][0], bfr[nb][1], bfr[nb][2], bfr[nb][3], addr);
            }
            #pragma unroll
            for (int j = 0; j < 8; j++) {
                mma16816(sacc[j], qf[ks],     bfr[j >> 1][(j & 1) * 2], bfr[j >> 1][(j & 1) * 2 + 1]);
                mma16816(sacc[j], qf[ks + 4], bfr[j >> 1][(j & 1) * 2], bfr[j >> 1][(j & 1) * 2 + 1]);
            }
        }
        #pragma unroll
        for (int ks = 0; ks < 4; ks++) {
            uint32_t bfr[4][4];
            #pragma unroll
            for (int nb = 0; nb < 4; nb++) {
                uint32_t addr = sK + (uint32_t)((nb * 16 + b_r2) * FQB + (64 + ks * 16 + b_c) * 2);
                ldsm_x4(bfr[nb][0], bfr[nb][1], bfr[nb][2], bfr[nb][3], addr);
            }
            #pragma unroll
            for (int j = 0; j < 8; j++)
                mma16816(sacc[j], qf[ks], bfr[j >> 1][(j & 1) * 2], bfr[j >> 1][(j & 1) * 2 + 1]);
        }

        // ---- online softmax (scale pre-folded into q) ----
        #pragma unroll
        for (int hf = 0; hf < 2; hf++) {
            float mt = -1e30f;
            #pragma unroll
            for (int j = 0; j < 8; j++)
                mt = fmaxf(mt, fmaxf(sacc[j][2*hf], sacc[j][2*hf+1]));
            mt = fmaxf(mt, __shfl_xor_sync(0xffffffffu, mt, 1));
            mt = fmaxf(mt, __shfl_xor_sync(0xffffffffu, mt, 2));
            float mn = fmaxf(mrow[hf], mt);
            float alpha = __expf(mrow[hf] - mn);
            mrow[hf] = mn;
            float lt = 0.f;
            #pragma unroll
            for (int j = 0; j < 8; j++) {
                float p0 = __expf(sacc[j][2*hf] - mn);
                float p1 = __expf(sacc[j][2*hf+1] - mn);
                sacc[j][2*hf] = p0; sacc[j][2*hf+1] = p1;
                lt += p0 + p1;
            }
            lt += __shfl_xor_sync(0xffffffffu, lt, 1);
            lt += __shfl_xor_sync(0xffffffffu, lt, 2);
            lrow[hf] = lrow[hf] * alpha + lt;
            #pragma unroll
            for (int j = 0; j < 8; j++) { oacc[j][2*hf] *= alpha; oacc[j][2*hf+1] *= alpha; }
        }

        uint32_t ahi[4][4], alo[4][4];
        #pragma unroll
        for (int kk = 0; kk < 4; kk++) {
            #pragma unroll
            for (int q = 0; q < 4; q++) {
                int j = 2 * kk + (q >> 1);
                float p0 = sacc[j][(q & 1) * 2], p1 = sacc[j][(q & 1) * 2 + 1];
                float h0 = __bfloat162float(__float2bfloat16(p0));
                float h1 = __bfloat162float(__float2bfloat16(p1));
                ahi[kk][q] = packbf(h0, h1);
                alo[kk][q] = packbf(p0 - h0, p1 - h1);
            }
        }

        #pragma unroll
        for (int kk = 0; kk < 4; kk++) {
            uint32_t bfh[4][4];
            #pragma unroll
            for (int nb = 0; nb < 4; nb++) {
                uint32_t addr = sVh + (uint32_t)((kk * 16 + v_r) * FVB + (nb * 16 + v_c) * 2);
                ldsm_x4t(bfh[nb][0], bfh[nb][1], bfh[nb][2], bfh[nb][3], addr);
            }
            #pragma unroll
            for (int j = 0; j < 8; j++) {
                mma16816(oacc[j], ahi[kk], bfh[j >> 1][(j & 1) * 2], bfh[j >> 1][(j & 1) * 2 + 1]);
                mma16816(oacc[j], alo[kk], bfh[j >> 1][(j & 1) * 2], bfh[j >> 1][(j & 1) * 2 + 1]);
            }
            uint32_t bfl[4][4];
            #pragma unroll
            for (int nb = 0; nb < 4; nb++) {
                uint32_t addr = sVl + (uint32_t)((kk * 16 + v_r) * FVB + (nb * 16 + v_c) * 2);
                ldsm_x4t(bfl[nb][0], bfl[nb][1], bfl[nb][2], bfl[nb][3], addr);
            }
            #pragma unroll
            for (int j = 0; j < 8; j++)
                mma16816(oacc[j], ahi[kk], bfl[j >> 1][(j & 1) * 2], bfl[j >> 1][(j & 1) * 2 + 1]);
        }
        __syncthreads();
    }

    float inv0 = 1.f / lrow[0], inv1 = 1.f / lrow[1];
    int r0 = qt * 128 + w * 16 + (lane >> 2);
    size_t row0 = (size_t)(b * NS + r0) * 2 * ND;
    size_t row1 = row0 + (size_t)8 * 2 * ND;
    #pragma unroll
    for (int j = 0; j < 8; j++) {
        int col = hd * 64 + j * 8 + (lane & 3) * 2;
        store_aug2(g_attn_aug, row0, ND, col, oacc[j][0] * inv0, oacc[j][1] * inv0);
        store_aug2(g_attn_aug, row1, ND, col, oacc[j][2] * inv1, oacc[j][3] * inv1);
    }
}

// ====================== HMMA bf16 GEMM (4-stage, A-wrap) ====================
#define HG_PAD    40
#define HG_STAGE  (2 * 128 * HG_PAD * 2)   // 20480
#define HG_SMEM   (4 * HG_STAGE)           // 81920

template<int EPI>
__global__ __launch_bounds__(256)
void hmma_gemm(const __nv_bfloat16* __restrict__ A, const __nv_bfloat16* __restrict__ Bt,
               float* __restrict__ C, int M, int N, int Kb,
               const float* __restrict__ bias,
               const float* __restrict__ e1, const float* __restrict__ e2)
{
    extern __shared__ char smc[];
    const int tid = threadIdx.x;
    const int wid = tid >> 5, lane = tid & 31;
    const int m0 = blockIdx.y * 128, n0 = blockIdx.x * 128;
    const int wm = (wid >> 2) * 64, wn = (wid & 3) * 32;
    const uint32_t sbase = smem_u32(smc);
    const int Kp = 3 * Kb;
    const int Ka = 2 * Kb;

    const int q0 = tid, q1 = tid + 256;
    const int ra0 = q0 >> 2, ca0 = (q0 & 3);
    const int ra1 = q1 >> 2, ca1 = (q1 & 3);

    auto load_stage = [&](int s, int kk) {
        int kka = (kk >= Ka) ? kk - Ka : kk;
        uint32_t aS = sbase + s * HG_STAGE;
        uint32_t bS = aS + 128 * HG_PAD * 2;
        cp_async16(aS + ra0 * 80 + ca0 * 16, A + (size_t)(m0 + ra0) * Ka + kka + ca0 * 8);
        cp_async16(aS + ra1 * 80 + ca1 * 16, A + (size_t)(m0 + ra1) * Ka + kka + ca1 * 8);
        cp_async16(bS + ra0 * 80 + ca0 * 16, Bt + (size_t)(n0 + ra0) * Kp + kk + ca0 * 8);
        cp_async16(bS + ra1 * 80 + ca1 * 16, Bt + (size_t)(n0 + ra1) * Kp + kk + ca1 * 8);
        CP_COMMIT();
    };

    const int KT = Kp >> 5;
    load_stage(0, 0);
    load_stage(1, 32);
    load_stage(2, 64);

    float acc[16][4];
    #pragma unroll
    for (int f = 0; f < 16; f++)
        #pragma unroll
        for (int e = 0; e < 4; e++) acc[f][e] = 0.f;

    const int a_r = (lane & 15);
    const int a_c = (lane >> 4) * 8;
    const int b_g = lane >> 3;
    const int b_r = (b_g >> 1) * 8 + (lane & 7);
    const int b_c = (b_g & 1) * 8;

    for (int kt = 0; kt < KT; kt++) {
        CP_WAIT2();
        __syncthreads();
        if (kt + 3 < KT) load_stage((kt + 3) & 3, (kt + 3) * 32);

        uint32_t aS = sbase + (kt & 3) * HG_STAGE;
        uint32_t bS = aS + 128 * HG_PAD * 2;

        #pragma unroll
        for (int ks = 0; ks < 2; ks++) {
            uint32_t af[4][4];
            #pragma unroll
            for (int mf = 0; mf < 4; mf++) {
                uint32_t addr = aS + (uint32_t)((wm + mf * 16 + a_r) * 80 + (ks * 16 + a_c) * 2);
                ldsm_x4(af[mf][0], af[mf][1], af[mf][2], af[mf][3], addr);
            }
            uint32_t bfr[2][4];
            #pragma unroll
            for (int nb = 0; nb < 2; nb++) {
                uint32_t addr = bS + (uint32_t)((wn + nb * 16 + b_r) * 80 + (ks * 16 + b_c) * 2);
                ldsm_x4(bfr[nb][0], bfr[nb][1], bfr[nb][2], bfr[nb][3], addr);
            }
            #pragma unroll
            for (int mf = 0; mf < 4; mf++)
                #pragma unroll
                for (int nf = 0; nf < 4; nf++) {
                    int nb = nf >> 1, pr = (nf & 1) * 2;
                    mma16816(acc[mf * 4 + nf], af[mf], bfr[nb][pr], bfr[nb][pr + 1]);
                }
        }
    }

    #pragma unroll
    for (int mf = 0; mf < 4; mf++) {
        #pragma unroll
        for (int nf = 0; nf < 4; nf++) {
            float* a = acc[mf * 4 + nf];
            int col = n0 + wn + nf * 8 + (lane & 3) * 2;
            #pragma unroll
            for (int half = 0; half < 2; half++) {
                int row = m0 + wm + mf * 16 + (lane >> 2) + half * 8;
                size_t idx = (size_t)row * N + col;
                float v0 = a[half * 2], v1 = a[half * 2 + 1];
                if (EPI == 0) {
                    if (bias) { v0 += bias[col]; v1 += bias[col + 1]; }
                    *(float2*)(C + idx) = make_float2(v0, v1);
                } else if (EPI == 1) {
                    float g0 = 1.f / (1.f + __expf(-(v0 + bias[col])));
                    float g1 = 1.f / (1.f + __expf(-(v1 + bias[col + 1])));
                    float2 ee1 = *(const float2*)(e1 + idx);
                    float2 ee2 = *(const float2*)(e2 + idx);
                    *(float2*)(C + idx) = make_float2(ee2.x + ee1.x * g0, ee2.y + ee1.y * g1);
                } else if (EPI == 2) {
                    float2 ee2 = *(const float2*)(e2 + idx);
                    *(float2*)(C + idx) = make_float2(ee2.x + v0 + bias[col],
                                                      ee2.y + v1 + bias[col + 1]);
                } else if (EPI == 3) {
                    *(float2*)(C + idx) = make_float2(v0, v1);
                    __nv_bfloat16* Ca = (__nv_bfloat16*)(uintptr_t)e1;
                    store_aug2(Ca, (size_t)row * 2 * N, N, col, v0, v1);
                } else {
                    int j = col >> 1;
                    float g = v0 + bias[j];
                    float vv = v1 + bias[j + (N >> 1)];
                    float t = vv * (0.5f * g * (1.f + erff(g * 0.70710678118654752f)));
                    __nv_bfloat16 hi, lo; split_hi_lo(t, hi, lo);
                    __nv_bfloat16* T = (__nv_bfloat16*)(uintptr_t)e1;
                    size_t rb = (size_t)row * N;
                    T[rb + j] = hi;
                    T[rb + (N >> 1) + j] = lo;
                }
            }
        }
    }
}

// --------------------------------- launcher ---------------------------------
extern "C" void kernel_launch(void* const* d_in, const int* in_sizes, int n_in,
                              void* d_out, int out_size) {
    const float* x          = (const float*)d_in[0];
    const float* vs         = (const float*)d_in[3];
    const float* w_qkv      = (const float*)d_in[4];
    const float* w_out      = (const float*)d_in[5];
    const float* w_gate     = (const float*)d_in[6];
    const float* b_gate     = (const float*)d_in[7];
    const float* w_mlp_gate = (const float*)d_in[8];
    const float* b_mlp_gate = (const float*)d_in[9];
    const float* w_mlp_out  = (const float*)d_in[10];
    const float* b_mlp_out  = (const float*)d_in[11];
    float* out = (float*)d_out;

    float *p_qkv, *p_attnproj, *p_x1, *p_wrot;
    __nv_bfloat16 *p_h_aug, *p_attn_aug, *p_ap_aug, *p_h2_aug, *p_t_aug;
    __nv_bfloat16 *p_wqkvT, *p_woutT, *p_wgateT, *p_wmgT, *p_wmoT;
    cudaGetSymbolAddress((void**)&p_qkv, g_qkv);
    cudaGetSymbolAddress((void**)&p_attnproj, g_attnproj);
    cudaGetSymbolAddress((void**)&p_x1, g_x1);
    cudaGetSymbolAddress((void**)&p_wrot, g_wqkv_rot);
    cudaGetSymbolAddress((void**)&p_h_aug, g_h_aug);
    cudaGetSymbolAddress((void**)&p_attn_aug, g_attn_aug);
    cudaGetSymbolAddress((void**)&p_ap_aug, g_ap_aug);
    cudaGetSymbolAddress((void**)&p_h2_aug, g_h2_aug);
    cudaGetSymbolAddress((void**)&p_t_aug, g_t_aug);
    cudaGetSymbolAddress((void**)&p_wqkvT, g_wqkvT);
    cudaGetSymbolAddress((void**)&p_woutT, g_woutT);
    cudaGetSymbolAddress((void**)&p_wgateT, g_wgateT);
    cudaGetSymbolAddress((void**)&p_wmgT, g_wmgT);
    cudaGetSymbolAddress((void**)&p_wmoT, g_wmoT);

    cudaFuncSetAttribute(flash_hmma_kernel, cudaFuncAttributeMaxDynamicSharedMemorySize, FLS_SMEM);
    cudaFuncSetAttribute(hmma_gemm<0>, cudaFuncAttributeMaxDynamicSharedMemorySize, HG_SMEM);
    cudaFuncSetAttribute(hmma_gemm<1>, cudaFuncAttributeMaxDynamicSharedMemorySize, HG_SMEM);
    cudaFuncSetAttribute(hmma_gemm<2>, cudaFuncAttributeMaxDynamicSharedMemorySize, HG_SMEM);
    cudaFuncSetAttribute(hmma_gemm<3>, cudaFuncAttributeMaxDynamicSharedMemorySize, HG_SMEM);
    cudaFuncSetAttribute(hmma_gemm<4>, cudaFuncAttributeMaxDynamicSharedMemorySize, HG_SMEM);

    dim3 t32(32, 32);
    // Q build + fold Q^T into q,k weight columns (smem-staged premul)
    buildQ_kernel<<<1, 64>>>(vs);
    premul_qkv_kernel<<<ND, 256>>>(w_qkv, p_wrot);
    transpose_split_multi_kernel<<<4608, t32>>>(p_wrot, p_wqkvT, w_out, p_woutT,
                                                w_gate, p_wgateT, w_mlp_out, p_wmoT);
    transpose_split_perm_kernel<<<dim3(ND/64, 8*ND/32), t32>>>(w_mlp_gate, p_wmgT, ND, 8*ND);
    rope_tables_kernel<<<NS, 64>>>();

    // 1. h = split(rmsnorm(x))  [hi|lo]
    rmsnorm_split_kernel<<<NBS, 256>>>(x, p_h_aug);
    // 2. qkv = h @ w_qkv_rot  (q,k already rotated)
    hmma_gemm<0><<<dim3(THREE_D/128, NBS/128), 256, HG_SMEM>>>(
        p_h_aug, p_wqkvT, p_qkv, NBS, THREE_D, ND, nullptr, nullptr, nullptr);
    // 3. elementwise RoPE (in-thread pairs) + head transpose -> split bf16
    rope_apply_kernel<<<NBS, 256>>>(p_qkv);
    // 4. attention (HMMA) -> attn [hi|lo]  (post-rotation cancels in QK^T)
    flash_hmma_kernel<<<dim3(NS/128, NB*NH), 256, FLS_SMEM>>>();
    // 5. attnproj = attn @ w_out  (+ fused [hi|lo] split)
    hmma_gemm<3><<<dim3(ND/128, NBS/128), 256, HG_SMEM>>>(
        p_attn_aug, p_woutT, p_attnproj, NBS, ND, ND, nullptr,
        (const float*)p_ap_aug, nullptr);
    // 6. x1 = x + attnproj * sigmoid(attnproj @ w_gate + b_gate)
    hmma_gemm<1><<<dim3(ND/128, NBS/128), 256, HG_SMEM>>>(
        p_ap_aug, p_wgateT, p_x1, NBS, ND, ND, b_gate, p_attnproj, x);
    // 7. h2 = split(rmsnorm(x1))
    rmsnorm_split_kernel<<<NBS, 256>>>(p_x1, p_h2_aug);
    // 8. fused mlp_gate GEMM + GLU -> t [hi|lo]   (permuted weights)
    hmma_gemm<4><<<dim3(8*ND/128, NBS/128), 256, HG_SMEM>>>(
        p_h2_aug, p_wmgT, p_x1 /*unused*/, NBS, 8*ND, ND, b_mlp_gate,
        (const float*)p_t_aug, nullptr);
    // 9. out = x1 + t @ w_mlp_out + b
    hmma_gemm<2><<<dim3(ND/128, NBS/128), 256, HG_SMEM>>>(
        p_t_aug, p_wmoT, out, NBS, ND, 4*ND, b_mlp_out, nullptr, p_x1);
}